// round 6
// baseline (speedup 1.0000x reference)
#include <cuda_runtime.h>

#define NN 50000
#define EE 1600000

// ---------------- scratch (device globals; zero-initialized at load) -------
__device__ float g_h[NN * 64];      // GEMM output (per-layer features)
__device__ float g_agg[NN * 64];    // post-pass output (next GEMM input)
__device__ float g_acc[NN * 64];    // edge-parallel accumulator (INVARIANT: zero at entry)
__device__ float g_asrc[NN * 4];
__device__ float g_adst[NN * 4];
__device__ float g_sum[NN * 4];     // softmax denominators, edges only (INVARIANT: zero)
__device__ int   g_rowptr[NN + 1];
__device__ int   g_cursor[NN];      // INVARIANT: zero at entry (restored by k_post4 L0)
__device__ int   g_srcs[EE];        // CSR columns (dst-sorted)
__device__ int   g_dsts[EE];        // dst per CSR slot
__device__ float g_stat[256];       // [0:128) raw stats (zero at entry; restored by
                                    // k_bnfinal), [128:192) scale, [192:256) shift

__device__ __forceinline__ float neg_inf() { return __int_as_float(0xff800000); }
__device__ __forceinline__ float lrelu(float e) { return fmaxf(e, 0.2f * e); }

// ---------------- CSR build -------------------------------------------------
__global__ void k_count(const int* __restrict__ ei) {
    int e = blockIdx.x * blockDim.x + threadIdx.x;
    if (e < EE) atomicAdd(&g_cursor[ei[EE + e]], 1);
}

__global__ void k_scan() {
    __shared__ int part[1024];
    const int t = threadIdx.x;
    const int CH = (NN + 1023) / 1024;
    const int start = t * CH;
    int sum = 0;
    for (int i = 0; i < CH; i++) {
        int v = start + i;
        if (v < NN) sum += g_cursor[v];
    }
    part[t] = sum;
    __syncthreads();
    for (int off = 1; off < 1024; off <<= 1) {
        int v = (t >= off) ? part[t - off] : 0;
        __syncthreads();
        part[t] += v;
        __syncthreads();
    }
    int run = (t > 0) ? part[t - 1] : 0;
    for (int i = 0; i < CH; i++) {
        int v = start + i;
        if (v < NN) {
            int d = g_cursor[v];
            g_rowptr[v] = run;
            g_cursor[v] = run;
            run += d;
        }
    }
    if (t == 1023) g_rowptr[NN] = part[1023];
}

__global__ void k_scatter(const int* __restrict__ ei) {
    int e = blockIdx.x * blockDim.x + threadIdx.x;
    if (e < EE) {
        int s = ei[e];
        int d = ei[EE + e];
        int pos = atomicAdd(&g_cursor[d], 1);
        g_srcs[pos] = s;
        g_dsts[pos] = d;
    }
}

// ---------------- SGEMM + fused alpha epilogue ------------------------------
template <int K, int NO, bool BN, int H>
__global__ __launch_bounds__(256) void k_gemm(const float* __restrict__ A,
                                              const float* __restrict__ W,
                                              float* __restrict__ C,
                                              const float* __restrict__ a_s,
                                              const float* __restrict__ a_d) {
    __shared__ float As[64][36];
    __shared__ float Ws[32][64];
    const int tid = threadIdx.x;
    const int ty = tid >> 4;
    const int tx = tid & 15;
    const int m0 = blockIdx.x * 64;
    const int lr = tid >> 3;
    const int lc = (tid & 7) * 4;
    float acc[4][4] = {};

    for (int kt = 0; kt < K; kt += 32) {
        float4 sc, sh;
        if (BN) {
            sc = *reinterpret_cast<const float4*>(&g_stat[128 + kt + lc]);
            sh = *reinterpret_cast<const float4*>(&g_stat[192 + kt + lc]);
        }
#pragma unroll
        for (int rr = 0; rr < 64; rr += 32) {
            int row = m0 + lr + rr;
            float4 v = make_float4(0.f, 0.f, 0.f, 0.f);
            if (row < NN)
                v = *reinterpret_cast<const float4*>(A + (size_t)row * K + kt + lc);
            if (BN) {
                v.x = fmaxf(v.x * sc.x + sh.x, 0.f);
                v.y = fmaxf(v.y * sc.y + sh.y, 0.f);
                v.z = fmaxf(v.z * sc.z + sh.z, 0.f);
                v.w = fmaxf(v.w * sc.w + sh.w, 0.f);
            }
            *reinterpret_cast<float4*>(&As[lr + rr][lc]) = v;
        }
#pragma unroll
        for (int kk = 0; kk < 32; kk += 16) {
            int k = ty + kk;
            int c = tx * 4;
            float4 v = make_float4(0.f, 0.f, 0.f, 0.f);
            if (NO == 64 || c < NO)
                v = *reinterpret_cast<const float4*>(W + (size_t)(kt + k) * NO + c);
            *reinterpret_cast<float4*>(&Ws[k][c]) = v;
        }
        __syncthreads();
#pragma unroll
        for (int k = 0; k < 32; k++) {
            float a0 = As[ty * 4 + 0][k];
            float a1 = As[ty * 4 + 1][k];
            float a2 = As[ty * 4 + 2][k];
            float a3 = As[ty * 4 + 3][k];
            float4 b = *reinterpret_cast<const float4*>(&Ws[k][tx * 4]);
            acc[0][0] += a0 * b.x; acc[0][1] += a0 * b.y; acc[0][2] += a0 * b.z; acc[0][3] += a0 * b.w;
            acc[1][0] += a1 * b.x; acc[1][1] += a1 * b.y; acc[1][2] += a1 * b.z; acc[1][3] += a1 * b.w;
            acc[2][0] += a2 * b.x; acc[2][1] += a2 * b.y; acc[2][2] += a2 * b.z; acc[2][3] += a2 * b.w;
            acc[3][0] += a3 * b.x; acc[3][1] += a3 * b.y; acc[3][2] += a3 * b.z; acc[3][3] += a3 * b.w;
        }
        __syncthreads();
    }
#pragma unroll
    for (int i = 0; i < 4; i++) {
        int row = m0 + ty * 4 + i;
        if (row < NN && (NO == 64 || tx * 4 < NO)) {
            float4 v = make_float4(acc[i][0], acc[i][1], acc[i][2], acc[i][3]);
            *reinterpret_cast<float4*>(C + (size_t)row * NO + tx * 4) = v;
        }
    }
    const bool colok = (NO == 64) || (tx * 4 < NO);
    float4 av = make_float4(0.f, 0.f, 0.f, 0.f), dv = av;
    if (colok) {
        av = *reinterpret_cast<const float4*>(a_s + tx * 4);
        dv = *reinterpret_cast<const float4*>(a_d + tx * 4);
    }
#pragma unroll
    for (int i = 0; i < 4; i++) {
        float ps = acc[i][0] * av.x + acc[i][1] * av.y + acc[i][2] * av.z + acc[i][3] * av.w;
        float pd = acc[i][0] * dv.x + acc[i][1] * dv.y + acc[i][2] * dv.z + acc[i][3] * dv.w;
        ps += __shfl_xor_sync(0xffffffffu, ps, 1);
        pd += __shfl_xor_sync(0xffffffffu, pd, 1);
        ps += __shfl_xor_sync(0xffffffffu, ps, 2);
        pd += __shfl_xor_sync(0xffffffffu, pd, 2);
        int row = m0 + ty * 4 + i;
        if (H == 4) {
            if ((tx & 3) == 0 && row < NN) {
                g_asrc[row * 4 + (tx >> 2)] = ps;
                g_adst[row * 4 + (tx >> 2)] = pd;
            }
        } else {
            ps += __shfl_xor_sync(0xffffffffu, ps, 4);
            pd += __shfl_xor_sync(0xffffffffu, pd, 4);
            ps += __shfl_xor_sync(0xffffffffu, ps, 8);
            pd += __shfl_xor_sync(0xffffffffu, pd, 8);
            if (tx == 0 && row < NN) {
                g_asrc[row] = ps;
                g_adst[row] = pd;
            }
        }
    }
}

// ---------------- EDGE-PARALLEL aggregation, H=4 C=16 -----------------------
// One warp per 8 consecutive CSR edges. Segmented accumulation over dst runs,
// flushed via RED (atomicAdd, no return). No per-node serial walk.
__global__ __launch_bounds__(256) void k_eagg4(const float* __restrict__ h) {
    const int tid = threadIdx.x;
    const int lane = tid & 31;
    const int gw = (blockIdx.x * 256 + tid) >> 5;
    const int base = gw * 8;
    if (base >= EE) return;
    const int c0 = lane, c1 = lane + 32;
    const int h0 = lane >> 4;       // head of c0: 0/1
    const int h1 = 2 + h0;          // head of c1: 2/3

    int s[8], d[8];
#pragma unroll
    for (int j = 0; j < 8; j++) s[j] = g_srcs[base + j];   // broadcast, sequential
#pragma unroll
    for (int j = 0; j < 8; j++) d[j] = g_dsts[base + j];
    float w0[8], w1[8];
#pragma unroll
    for (int j = 0; j < 8; j++) {
        float as0 = g_asrc[s[j] * 4 + h0];
        float as1 = g_asrc[s[j] * 4 + h1];
        float ad0 = g_adst[d[j] * 4 + h0];
        float ad1 = g_adst[d[j] * 4 + h1];
        w0[j] = __expf(lrelu(as0 + ad0));
        w1[j] = __expf(lrelu(as1 + ad1));
    }
    float hv0[8], hv1[8];
#pragma unroll
    for (int j = 0; j < 8; j++) {
        hv0[j] = h[(size_t)s[j] * 64 + c0];
        hv1[j] = h[(size_t)s[j] * 64 + c1];
    }
    float acc0 = 0.f, acc1 = 0.f, ss0 = 0.f, ss1 = 0.f;
    int dcur = d[0];
#pragma unroll
    for (int j = 0; j < 8; j++) {
        if (d[j] != dcur) {   // uniform across warp
            atomicAdd(&g_acc[(size_t)dcur * 64 + c0], acc0);
            atomicAdd(&g_acc[(size_t)dcur * 64 + c1], acc1);
            if ((lane & 15) == 0) {
                atomicAdd(&g_sum[dcur * 4 + h0], ss0);
                atomicAdd(&g_sum[dcur * 4 + h1], ss1);
            }
            acc0 = acc1 = ss0 = ss1 = 0.f;
            dcur = d[j];
        }
        acc0 += w0[j] * hv0[j];
        acc1 += w1[j] * hv1[j];
        ss0 += w0[j];
        ss1 += w1[j];
    }
    atomicAdd(&g_acc[(size_t)dcur * 64 + c0], acc0);
    atomicAdd(&g_acc[(size_t)dcur * 64 + c1], acc1);
    if ((lane & 15) == 0) {
        atomicAdd(&g_sum[dcur * 4 + h0], ss0);
        atomicAdd(&g_sum[dcur * 4 + h1], ss1);
    }
}

// ---------------- EDGE-PARALLEL aggregation, H=1 C=40 -----------------------
__global__ __launch_bounds__(256) void k_eagg1(const float* __restrict__ h) {
    const int tid = threadIdx.x;
    const int lane = tid & 31;
    const int gw = (blockIdx.x * 256 + tid) >> 5;
    const int base = gw * 8;
    if (base >= EE) return;
    const int c0 = lane, c1 = lane + 32;
    const bool use1 = lane < 8;

    int s[8], d[8];
#pragma unroll
    for (int j = 0; j < 8; j++) s[j] = g_srcs[base + j];
#pragma unroll
    for (int j = 0; j < 8; j++) d[j] = g_dsts[base + j];
    float w[8];
#pragma unroll
    for (int j = 0; j < 8; j++)
        w[j] = __expf(lrelu(g_asrc[s[j]] + g_adst[d[j]]));
    float hv0[8], hv1[8];
#pragma unroll
    for (int j = 0; j < 8; j++) {
        hv0[j] = h[(size_t)s[j] * 40 + c0];
        hv1[j] = use1 ? h[(size_t)s[j] * 40 + c1] : 0.f;
    }
    float acc0 = 0.f, acc1 = 0.f, ss = 0.f;
    int dcur = d[0];
#pragma unroll
    for (int j = 0; j < 8; j++) {
        if (d[j] != dcur) {
            atomicAdd(&g_acc[(size_t)dcur * 64 + c0], acc0);
            if (use1) atomicAdd(&g_acc[(size_t)dcur * 64 + c1], acc1);
            if (lane == 0) atomicAdd(&g_sum[dcur * 4], ss);
            acc0 = acc1 = ss = 0.f;
            dcur = d[j];
        }
        acc0 += w[j] * hv0[j];
        acc1 += w[j] * hv1[j];
        ss += w[j];
    }
    atomicAdd(&g_acc[(size_t)dcur * 64 + c0], acc0);
    if (use1) atomicAdd(&g_acc[(size_t)dcur * 64 + c1], acc1);
    if (lane == 0) atomicAdd(&g_sum[dcur * 4], ss);
}

// ---------------- post-pass H=4: self-loop + normalize + bias + BN stats ----
// Also restores zero invariants on g_acc / g_sum (and g_cursor when CLRCUR).
template <bool CLRCUR>
__global__ __launch_bounds__(256) void k_post4(const float* __restrict__ h,
                                               const float* __restrict__ bias,
                                               float* __restrict__ out) {
    __shared__ float shs[256], shq[256];
    const int idx = blockIdx.x * 256 + threadIdx.x;  // grid covers NN*64 exactly
    const int v = idx >> 6;
    const int c = idx & 63;
    const int head = c >> 4;
    float ws = __expf(lrelu(g_asrc[v * 4 + head] + g_adst[v * 4 + head]));
    float o = (g_acc[idx] + ws * h[idx]) / (g_sum[v * 4 + head] + ws + 1e-16f) + bias[c];
    out[idx] = o;
    g_acc[idx] = 0.f;
    if (c < 4) g_sum[v * 4 + c] = 0.f;
    if (CLRCUR && c == 0) g_cursor[v] = 0;
    // BN stats: block holds 4 consecutive nodes; reduce per channel, RED out
    shs[threadIdx.x] = o;
    shq[threadIdx.x] = o * o;
    __syncthreads();
    if (threadIdx.x < 64) {
        float s = shs[threadIdx.x] + shs[threadIdx.x + 64] + shs[threadIdx.x + 128] + shs[threadIdx.x + 192];
        float q = shq[threadIdx.x] + shq[threadIdx.x + 64] + shq[threadIdx.x + 128] + shq[threadIdx.x + 192];
        atomicAdd(&g_stat[threadIdx.x], s);
        atomicAdd(&g_stat[64 + threadIdx.x], q);
    }
}

// ---------------- post-pass H=1: self-loop + normalize + bias + log_softmax -
__global__ __launch_bounds__(256) void k_post1(const float* __restrict__ h,
                                               const float* __restrict__ bias,
                                               float* __restrict__ out) {
    int gw = (blockIdx.x * blockDim.x + threadIdx.x) >> 5;
    int lane = threadIdx.x & 31;
    if (gw >= NN) return;
    const int c0 = lane, c1 = lane + 32;
    const bool use1 = lane < 8;
    float ws = __expf(lrelu(g_asrc[gw] + g_adst[gw]));
    float inv = 1.f / (g_sum[gw * 4] + ws + 1e-16f);
    float a0 = g_acc[(size_t)gw * 64 + c0];
    float a1 = use1 ? g_acc[(size_t)gw * 64 + c1] : 0.f;
    float o0 = (a0 + ws * h[(size_t)gw * 40 + c0]) * inv + bias[c0];
    float o1 = use1 ? ((a1 + ws * h[(size_t)gw * 40 + c1]) * inv + bias[c1]) : neg_inf();
    // restore invariants
    g_acc[(size_t)gw * 64 + c0] = 0.f;
    if (use1) g_acc[(size_t)gw * 64 + c1] = 0.f;
    if (lane == 0) g_sum[gw * 4] = 0.f;
    // log-softmax over 40
    float m = fmaxf(o0, o1);
#pragma unroll
    for (int off = 16; off; off >>= 1) m = fmaxf(m, __shfl_xor_sync(0xffffffffu, m, off));
    float se = __expf(o0 - m) + (use1 ? __expf(o1 - m) : 0.f);
#pragma unroll
    for (int off = 16; off; off >>= 1) se += __shfl_xor_sync(0xffffffffu, se, off);
    float ls = __logf(se);
    out[(size_t)gw * 40 + c0] = o0 - m - ls;
    if (use1) out[(size_t)gw * 40 + c1] = o1 - m - ls;
}

// ---------------- BN finalize (restores zero-stat invariant) ----------------
__global__ void k_bnfinal(const float* __restrict__ g, const float* __restrict__ beta) {
    int c = threadIdx.x;
    if (c >= 64) return;
    float mean = g_stat[c] * (1.0f / NN);
    float var = g_stat[64 + c] * (1.0f / NN) - mean * mean;
    float sc = g[c] * rsqrtf(var + 1e-5f);
    g_stat[128 + c] = sc;
    g_stat[192 + c] = beta[c] - mean * sc;
    g_stat[c] = 0.f;
    g_stat[64 + c] = 0.f;
}

// ---------------- launch ----------------------------------------------------
extern "C" void kernel_launch(void* const* d_in, const int* in_sizes, int n_in,
                              void* d_out, int out_size) {
    const float* x   = (const float*)d_in[0];
    const int*   ei  = (const int*)d_in[1];
    const float* W0  = (const float*)d_in[2];
    const float* as0 = (const float*)d_in[3];
    const float* ad0 = (const float*)d_in[4];
    const float* b0  = (const float*)d_in[5];
    const float* g0  = (const float*)d_in[6];
    const float* be0 = (const float*)d_in[7];
    const float* W1  = (const float*)d_in[8];
    const float* as1 = (const float*)d_in[9];
    const float* ad1 = (const float*)d_in[10];
    const float* b1  = (const float*)d_in[11];
    const float* g1  = (const float*)d_in[12];
    const float* be1 = (const float*)d_in[13];
    const float* W2  = (const float*)d_in[14];
    const float* as2 = (const float*)d_in[15];
    const float* ad2 = (const float*)d_in[16];
    const float* b2  = (const float*)d_in[17];
    float* out = (float*)d_out;

    const int gemmGrid = (NN + 63) / 64;
    const int edgeGrid = (EE / 8 + 7) / 8;      // warps = EE/8, 8 warps/block
    const int postGrid = NN * 64 / 256;         // 12500
    const int nodeWarpGrid = (NN + 7) / 8;

    k_count<<<(EE + 255) / 256, 256>>>(ei);                               // 1
    k_scan<<<1, 1024>>>();                                                // 2
    k_scatter<<<(EE + 255) / 256, 256>>>(ei);                             // 3

    // ---- layer 0 ----
    k_gemm<128, 64, false, 4><<<gemmGrid, 256>>>(x, W0, g_h, as0, ad0);   // 4 <- profile slot
    k_eagg4<<<edgeGrid, 256>>>(g_h);                                      // 5
    k_post4<true><<<postGrid, 256>>>(g_h, b0, g_agg);                     // 6 (zeros cursor)
    k_bnfinal<<<1, 64>>>(g0, be0);                                        // 7

    // ---- layer 1 ----
    k_gemm<64, 64, true, 4><<<gemmGrid, 256>>>(g_agg, W1, g_h, as1, ad1); // 8
    k_eagg4<<<edgeGrid, 256>>>(g_h);                                      // 9
    k_post4<false><<<postGrid, 256>>>(g_h, b1, g_agg);                    // 10
    k_bnfinal<<<1, 64>>>(g1, be1);                                        // 11

    // ---- layer 2 ----
    k_gemm<64, 40, true, 1><<<gemmGrid, 256>>>(g_agg, W2, g_h, as2, ad2); // 12
    k_eagg1<<<edgeGrid, 256>>>(g_h);                                      // 13
    k_post1<<<nodeWarpGrid, 256>>>(g_h, b2, out);                         // 14
}

// round 7
// speedup vs baseline: 1.2442x; 1.2442x over previous
#include <cuda_runtime.h>

#define NN 50000
#define EE 1600000
#define PE (EE / 8)   // probe edge count

// ---------------- scratch (device globals; zero-initialized at load) -------
__device__ float g_h[NN * 64];      // GEMM output (per-layer features)
__device__ float g_agg[NN * 64];    // post-pass output (next GEMM input)
__device__ float g_acc[NN * 64];    // edge-parallel accumulator (INVARIANT: zero at entry)
__device__ float g_pacc[NN * 64];   // probe scratch (never read; no invariant needed)
__device__ float g_psum[NN * 4];    // probe scratch sums
__device__ float g_asrc[NN * 4];
__device__ float g_adst[NN * 4];
__device__ float g_sum[NN * 4];     // softmax denominators, edges only (INVARIANT: zero)
__device__ int   g_rowptr[NN + 1];
__device__ int   g_cursor[NN];      // INVARIANT: zero at entry (restored by k_post4 L0)
__device__ int   g_srcs[EE];        // CSR columns (dst-sorted)
__device__ int   g_dsts[EE];        // dst per CSR slot
__device__ float g_stat[256];       // [0:128) raw stats (zero at entry; restored by
                                    // k_bnfinal), [128:192) scale, [192:256) shift

__device__ __forceinline__ float neg_inf() { return __int_as_float(0xff800000); }
__device__ __forceinline__ float lrelu(float e) { return fmaxf(e, 0.2f * e); }

// ---------------- CSR build -------------------------------------------------
__global__ void k_count(const int* __restrict__ ei) {
    int e = blockIdx.x * blockDim.x + threadIdx.x;
    if (e < EE) atomicAdd(&g_cursor[ei[EE + e]], 1);
}

__global__ void k_scan() {
    __shared__ int part[1024];
    const int t = threadIdx.x;
    const int CH = (NN + 1023) / 1024;
    const int start = t * CH;
    int sum = 0;
    for (int i = 0; i < CH; i++) {
        int v = start + i;
        if (v < NN) sum += g_cursor[v];
    }
    part[t] = sum;
    __syncthreads();
    for (int off = 1; off < 1024; off <<= 1) {
        int v = (t >= off) ? part[t - off] : 0;
        __syncthreads();
        part[t] += v;
        __syncthreads();
    }
    int run = (t > 0) ? part[t - 1] : 0;
    for (int i = 0; i < CH; i++) {
        int v = start + i;
        if (v < NN) {
            int d = g_cursor[v];
            g_rowptr[v] = run;
            g_cursor[v] = run;
            run += d;
        }
    }
    if (t == 1023) g_rowptr[NN] = part[1023];
}

__global__ void k_scatter(const int* __restrict__ ei) {
    int e = blockIdx.x * blockDim.x + threadIdx.x;
    if (e < EE) {
        int s = ei[e];
        int d = ei[EE + e];
        int pos = atomicAdd(&g_cursor[d], 1);
        g_srcs[pos] = s;
        g_dsts[pos] = d;
    }
}

// ---------------- PROBE: replicates edge-phase access pattern ---------------
// Raw edges + x gathers + exp + chunk-level RED flush into write-only scratch.
// Runs at slot 4 so ncu captures the edge-kernel roofline. Deterministic work;
// scratch is never read, so accumulated values don't affect the output.
__global__ __launch_bounds__(256) void k_probe(const int* __restrict__ ei,
                                               const float* __restrict__ x) {
    const int tid = threadIdx.x;
    const int lane = tid & 31;
    const int gw = (blockIdx.x * 256 + tid) >> 5;
    const int base = gw * 8;
    if (base >= PE) return;
    const int c0 = lane, c1 = lane + 32;
    const int h0 = lane >> 4, h1 = 2 + h0;

    int s[8], d[8];
#pragma unroll
    for (int j = 0; j < 8; j++) s[j] = ei[base + j];          // broadcast
#pragma unroll
    for (int j = 0; j < 8; j++) d[j] = ei[EE + base + j];
    float w0[8], w1[8];
#pragma unroll
    for (int j = 0; j < 8; j++) {                              // random 16B gathers
        float4 av = *reinterpret_cast<const float4*>(&x[(size_t)s[j] * 128]);
        float4 dv = *reinterpret_cast<const float4*>(&x[(size_t)d[j] * 128]);
        w0[j] = __expf(lrelu(av.x + dv.x));
        w1[j] = __expf(lrelu(av.y + dv.y));
    }
    float hv0[8], hv1[8];
#pragma unroll
    for (int j = 0; j < 8; j++) {                              // random 128B row gathers
        hv0[j] = x[(size_t)s[j] * 128 + c0];
        hv1[j] = x[(size_t)s[j] * 128 + 64 + c1];
    }
    float acc0 = 0.f, acc1 = 0.f, ss0 = 0.f, ss1 = 0.f;
#pragma unroll
    for (int j = 0; j < 8; j++) {
        acc0 += w0[j] * hv0[j];
        acc1 += w1[j] * hv1[j];
        ss0 += w0[j];
        ss1 += w1[j];
    }
    int dc = d[0];                                             // one flush per chunk
    atomicAdd(&g_pacc[(size_t)dc * 64 + c0], acc0);
    atomicAdd(&g_pacc[(size_t)dc * 64 + c1], acc1);
    if ((lane & 15) == 0) {
        atomicAdd(&g_psum[dc * 4 + h0], ss0);
        atomicAdd(&g_psum[dc * 4 + h1], ss1);
    }
}

// ---------------- SGEMM + fused alpha epilogue ------------------------------
template <int K, int NO, bool BN, int H>
__global__ __launch_bounds__(256) void k_gemm(const float* __restrict__ A,
                                              const float* __restrict__ W,
                                              float* __restrict__ C,
                                              const float* __restrict__ a_s,
                                              const float* __restrict__ a_d) {
    __shared__ float As[64][36];
    __shared__ float Ws[32][64];
    const int tid = threadIdx.x;
    const int ty = tid >> 4;
    const int tx = tid & 15;
    const int m0 = blockIdx.x * 64;
    const int lr = tid >> 3;
    const int lc = (tid & 7) * 4;
    float acc[4][4] = {};

    for (int kt = 0; kt < K; kt += 32) {
        float4 sc, sh;
        if (BN) {
            sc = *reinterpret_cast<const float4*>(&g_stat[128 + kt + lc]);
            sh = *reinterpret_cast<const float4*>(&g_stat[192 + kt + lc]);
        }
#pragma unroll
        for (int rr = 0; rr < 64; rr += 32) {
            int row = m0 + lr + rr;
            float4 v = make_float4(0.f, 0.f, 0.f, 0.f);
            if (row < NN)
                v = *reinterpret_cast<const float4*>(A + (size_t)row * K + kt + lc);
            if (BN) {
                v.x = fmaxf(v.x * sc.x + sh.x, 0.f);
                v.y = fmaxf(v.y * sc.y + sh.y, 0.f);
                v.z = fmaxf(v.z * sc.z + sh.z, 0.f);
                v.w = fmaxf(v.w * sc.w + sh.w, 0.f);
            }
            *reinterpret_cast<float4*>(&As[lr + rr][lc]) = v;
        }
#pragma unroll
        for (int kk = 0; kk < 32; kk += 16) {
            int k = ty + kk;
            int c = tx * 4;
            float4 v = make_float4(0.f, 0.f, 0.f, 0.f);
            if (NO == 64 || c < NO)
                v = *reinterpret_cast<const float4*>(W + (size_t)(kt + k) * NO + c);
            *reinterpret_cast<float4*>(&Ws[k][c]) = v;
        }
        __syncthreads();
#pragma unroll
        for (int k = 0; k < 32; k++) {
            float a0 = As[ty * 4 + 0][k];
            float a1 = As[ty * 4 + 1][k];
            float a2 = As[ty * 4 + 2][k];
            float a3 = As[ty * 4 + 3][k];
            float4 b = *reinterpret_cast<const float4*>(&Ws[k][tx * 4]);
            acc[0][0] += a0 * b.x; acc[0][1] += a0 * b.y; acc[0][2] += a0 * b.z; acc[0][3] += a0 * b.w;
            acc[1][0] += a1 * b.x; acc[1][1] += a1 * b.y; acc[1][2] += a1 * b.z; acc[1][3] += a1 * b.w;
            acc[2][0] += a2 * b.x; acc[2][1] += a2 * b.y; acc[2][2] += a2 * b.z; acc[2][3] += a2 * b.w;
            acc[3][0] += a3 * b.x; acc[3][1] += a3 * b.y; acc[3][2] += a3 * b.z; acc[3][3] += a3 * b.w;
        }
        __syncthreads();
    }
#pragma unroll
    for (int i = 0; i < 4; i++) {
        int row = m0 + ty * 4 + i;
        if (row < NN && (NO == 64 || tx * 4 < NO)) {
            float4 v = make_float4(acc[i][0], acc[i][1], acc[i][2], acc[i][3]);
            *reinterpret_cast<float4*>(C + (size_t)row * NO + tx * 4) = v;
        }
    }
    const bool colok = (NO == 64) || (tx * 4 < NO);
    float4 av = make_float4(0.f, 0.f, 0.f, 0.f), dv = av;
    if (colok) {
        av = *reinterpret_cast<const float4*>(a_s + tx * 4);
        dv = *reinterpret_cast<const float4*>(a_d + tx * 4);
    }
#pragma unroll
    for (int i = 0; i < 4; i++) {
        float ps = acc[i][0] * av.x + acc[i][1] * av.y + acc[i][2] * av.z + acc[i][3] * av.w;
        float pd = acc[i][0] * dv.x + acc[i][1] * dv.y + acc[i][2] * dv.z + acc[i][3] * dv.w;
        ps += __shfl_xor_sync(0xffffffffu, ps, 1);
        pd += __shfl_xor_sync(0xffffffffu, pd, 1);
        ps += __shfl_xor_sync(0xffffffffu, ps, 2);
        pd += __shfl_xor_sync(0xffffffffu, pd, 2);
        int row = m0 + ty * 4 + i;
        if (H == 4) {
            if ((tx & 3) == 0 && row < NN) {
                g_asrc[row * 4 + (tx >> 2)] = ps;
                g_adst[row * 4 + (tx >> 2)] = pd;
            }
        } else {
            ps += __shfl_xor_sync(0xffffffffu, ps, 4);
            pd += __shfl_xor_sync(0xffffffffu, pd, 4);
            ps += __shfl_xor_sync(0xffffffffu, ps, 8);
            pd += __shfl_xor_sync(0xffffffffu, pd, 8);
            if (tx == 0 && row < NN) {
                g_asrc[row] = ps;
                g_adst[row] = pd;
            }
        }
    }
}

// ---------------- EDGE-PARALLEL aggregation, H=4 C=16 -----------------------
__global__ __launch_bounds__(256) void k_eagg4(const float* __restrict__ h) {
    const int tid = threadIdx.x;
    const int lane = tid & 31;
    const int gw = (blockIdx.x * 256 + tid) >> 5;
    const int base = gw * 8;
    if (base >= EE) return;
    const int c0 = lane, c1 = lane + 32;
    const bool hi = lane >= 16;
    const int h0 = hi ? 1 : 0;
    const int h1 = 2 + h0;

    int s[8], d[8];
#pragma unroll
    for (int j = 0; j < 8; j++) s[j] = g_srcs[base + j];
#pragma unroll
    for (int j = 0; j < 8; j++) d[j] = g_dsts[base + j];
    float w0[8], w1[8];
#pragma unroll
    for (int j = 0; j < 8; j++) {
        float4 av = *reinterpret_cast<const float4*>(&g_asrc[s[j] * 4]);
        float4 dv = *reinterpret_cast<const float4*>(&g_adst[d[j] * 4]);
        float as0 = hi ? av.y : av.x;
        float as1 = hi ? av.w : av.z;
        float ad0 = hi ? dv.y : dv.x;
        float ad1 = hi ? dv.w : dv.z;
        w0[j] = __expf(lrelu(as0 + ad0));
        w1[j] = __expf(lrelu(as1 + ad1));
    }
    float hv0[8], hv1[8];
#pragma unroll
    for (int j = 0; j < 8; j++) {
        hv0[j] = h[(size_t)s[j] * 64 + c0];
        hv1[j] = h[(size_t)s[j] * 64 + c1];
    }
    float acc0 = 0.f, acc1 = 0.f, ss0 = 0.f, ss1 = 0.f;
    int dcur = d[0];
#pragma unroll
    for (int j = 0; j < 8; j++) {
        if (d[j] != dcur) {
            atomicAdd(&g_acc[(size_t)dcur * 64 + c0], acc0);
            atomicAdd(&g_acc[(size_t)dcur * 64 + c1], acc1);
            if ((lane & 15) == 0) {
                atomicAdd(&g_sum[dcur * 4 + h0], ss0);
                atomicAdd(&g_sum[dcur * 4 + h1], ss1);
            }
            acc0 = acc1 = ss0 = ss1 = 0.f;
            dcur = d[j];
        }
        acc0 += w0[j] * hv0[j];
        acc1 += w1[j] * hv1[j];
        ss0 += w0[j];
        ss1 += w1[j];
    }
    atomicAdd(&g_acc[(size_t)dcur * 64 + c0], acc0);
    atomicAdd(&g_acc[(size_t)dcur * 64 + c1], acc1);
    if ((lane & 15) == 0) {
        atomicAdd(&g_sum[dcur * 4 + h0], ss0);
        atomicAdd(&g_sum[dcur * 4 + h1], ss1);
    }
}

// ---------------- EDGE-PARALLEL aggregation, H=1 C=40 -----------------------
__global__ __launch_bounds__(256) void k_eagg1(const float* __restrict__ h) {
    const int tid = threadIdx.x;
    const int lane = tid & 31;
    const int gw = (blockIdx.x * 256 + tid) >> 5;
    const int base = gw * 8;
    if (base >= EE) return;
    const int c0 = lane, c1 = lane + 32;
    const bool use1 = lane < 8;

    int s[8], d[8];
#pragma unroll
    for (int j = 0; j < 8; j++) s[j] = g_srcs[base + j];
#pragma unroll
    for (int j = 0; j < 8; j++) d[j] = g_dsts[base + j];
    float w[8];
#pragma unroll
    for (int j = 0; j < 8; j++)
        w[j] = __expf(lrelu(g_asrc[s[j]] + g_adst[d[j]]));
    float hv0[8], hv1[8];
#pragma unroll
    for (int j = 0; j < 8; j++) {
        hv0[j] = h[(size_t)s[j] * 40 + c0];
        hv1[j] = use1 ? h[(size_t)s[j] * 40 + c1] : 0.f;
    }
    float acc0 = 0.f, acc1 = 0.f, ss = 0.f;
    int dcur = d[0];
#pragma unroll
    for (int j = 0; j < 8; j++) {
        if (d[j] != dcur) {
            atomicAdd(&g_acc[(size_t)dcur * 64 + c0], acc0);
            if (use1) atomicAdd(&g_acc[(size_t)dcur * 64 + c1], acc1);
            if (lane == 0) atomicAdd(&g_sum[dcur * 4], ss);
            acc0 = acc1 = ss = 0.f;
            dcur = d[j];
        }
        acc0 += w[j] * hv0[j];
        acc1 += w[j] * hv1[j];
        ss += w[j];
    }
    atomicAdd(&g_acc[(size_t)dcur * 64 + c0], acc0);
    if (use1) atomicAdd(&g_acc[(size_t)dcur * 64 + c1], acc1);
    if (lane == 0) atomicAdd(&g_sum[dcur * 4], ss);
}

// ---------------- post-pass H=4: self-loop + normalize + bias + BN stats ----
template <bool CLRCUR>
__global__ __launch_bounds__(256) void k_post4(const float* __restrict__ h,
                                               const float* __restrict__ bias,
                                               float* __restrict__ out) {
    __shared__ float shs[256], shq[256];
    const int idx = blockIdx.x * 256 + threadIdx.x;
    const int v = idx >> 6;
    const int c = idx & 63;
    const int head = c >> 4;
    float ws = __expf(lrelu(g_asrc[v * 4 + head] + g_adst[v * 4 + head]));
    float o = (g_acc[idx] + ws * h[idx]) / (g_sum[v * 4 + head] + ws + 1e-16f) + bias[c];
    out[idx] = o;
    g_acc[idx] = 0.f;
    if (c < 4) g_sum[v * 4 + c] = 0.f;
    if (CLRCUR && c == 0) g_cursor[v] = 0;
    shs[threadIdx.x] = o;
    shq[threadIdx.x] = o * o;
    __syncthreads();
    if (threadIdx.x < 64) {
        float s = shs[threadIdx.x] + shs[threadIdx.x + 64] + shs[threadIdx.x + 128] + shs[threadIdx.x + 192];
        float q = shq[threadIdx.x] + shq[threadIdx.x + 64] + shq[threadIdx.x + 128] + shq[threadIdx.x + 192];
        atomicAdd(&g_stat[threadIdx.x], s);
        atomicAdd(&g_stat[64 + threadIdx.x], q);
    }
}

// ---------------- post-pass H=1: self-loop + normalize + bias + log_softmax -
__global__ __launch_bounds__(256) void k_post1(const float* __restrict__ h,
                                               const float* __restrict__ bias,
                                               float* __restrict__ out) {
    int gw = (blockIdx.x * blockDim.x + threadIdx.x) >> 5;
    int lane = threadIdx.x & 31;
    if (gw >= NN) return;
    const int c0 = lane, c1 = lane + 32;
    const bool use1 = lane < 8;
    float ws = __expf(lrelu(g_asrc[gw] + g_adst[gw]));
    float inv = 1.f / (g_sum[gw * 4] + ws + 1e-16f);
    float a0 = g_acc[(size_t)gw * 64 + c0];
    float a1 = use1 ? g_acc[(size_t)gw * 64 + c1] : 0.f;
    float o0 = (a0 + ws * h[(size_t)gw * 40 + c0]) * inv + bias[c0];
    float o1 = use1 ? ((a1 + ws * h[(size_t)gw * 40 + c1]) * inv + bias[c1]) : neg_inf();
    g_acc[(size_t)gw * 64 + c0] = 0.f;
    if (use1) g_acc[(size_t)gw * 64 + c1] = 0.f;
    if (lane == 0) g_sum[gw * 4] = 0.f;
    float m = fmaxf(o0, o1);
#pragma unroll
    for (int off = 16; off; off >>= 1) m = fmaxf(m, __shfl_xor_sync(0xffffffffu, m, off));
    float se = __expf(o0 - m) + (use1 ? __expf(o1 - m) : 0.f);
#pragma unroll
    for (int off = 16; off; off >>= 1) se += __shfl_xor_sync(0xffffffffu, se, off);
    float ls = __logf(se);
    out[(size_t)gw * 40 + c0] = o0 - m - ls;
    if (use1) out[(size_t)gw * 40 + c1] = o1 - m - ls;
}

// ---------------- BN finalize (restores zero-stat invariant) ----------------
__global__ void k_bnfinal(const float* __restrict__ g, const float* __restrict__ beta) {
    int c = threadIdx.x;
    if (c >= 64) return;
    float mean = g_stat[c] * (1.0f / NN);
    float var = g_stat[64 + c] * (1.0f / NN) - mean * mean;
    float sc = g[c] * rsqrtf(var + 1e-5f);
    g_stat[128 + c] = sc;
    g_stat[192 + c] = beta[c] - mean * sc;
    g_stat[c] = 0.f;
    g_stat[64 + c] = 0.f;
}

// ---------------- launch ----------------------------------------------------
extern "C" void kernel_launch(void* const* d_in, const int* in_sizes, int n_in,
                              void* d_out, int out_size) {
    const float* x   = (const float*)d_in[0];
    const int*   ei  = (const int*)d_in[1];
    const float* W0  = (const float*)d_in[2];
    const float* as0 = (const float*)d_in[3];
    const float* ad0 = (const float*)d_in[4];
    const float* b0  = (const float*)d_in[5];
    const float* g0  = (const float*)d_in[6];
    const float* be0 = (const float*)d_in[7];
    const float* W1  = (const float*)d_in[8];
    const float* as1 = (const float*)d_in[9];
    const float* ad1 = (const float*)d_in[10];
    const float* b1  = (const float*)d_in[11];
    const float* g1  = (const float*)d_in[12];
    const float* be1 = (const float*)d_in[13];
    const float* W2  = (const float*)d_in[14];
    const float* as2 = (const float*)d_in[15];
    const float* ad2 = (const float*)d_in[16];
    const float* b2  = (const float*)d_in[17];
    float* out = (float*)d_out;

    const int gemmGrid = (NN + 63) / 64;
    const int edgeGrid = (EE / 8 + 7) / 8;
    const int probeGrid = (PE / 8 + 7) / 8;
    const int postGrid = NN * 64 / 256;
    const int nodeWarpGrid = (NN + 7) / 8;

    k_count<<<(EE + 255) / 256, 256>>>(ei);                               // 1
    k_scan<<<1, 1024>>>();                                                // 2
    k_scatter<<<(EE + 255) / 256, 256>>>(ei);                             // 3
    k_probe<<<probeGrid, 256>>>(ei, x);                                   // 4 <- PROFILE SLOT

    // ---- layer 0 ----
    k_gemm<128, 64, false, 4><<<gemmGrid, 256>>>(x, W0, g_h, as0, ad0);   // 5
    k_eagg4<<<edgeGrid, 256>>>(g_h);                                      // 6
    k_post4<true><<<postGrid, 256>>>(g_h, b0, g_agg);                     // 7 (zeros cursor)
    k_bnfinal<<<1, 64>>>(g0, be0);                                        // 8

    // ---- layer 1 ----
    k_gemm<64, 64, true, 4><<<gemmGrid, 256>>>(g_agg, W1, g_h, as1, ad1); // 9
    k_eagg4<<<edgeGrid, 256>>>(g_h);                                      // 10
    k_post4<false><<<postGrid, 256>>>(g_h, b1, g_agg);                    // 11
    k_bnfinal<<<1, 64>>>(g1, be1);                                        // 12

    // ---- layer 2 ----
    k_gemm<64, 40, true, 1><<<gemmGrid, 256>>>(g_agg, W2, g_h, as2, ad2); // 13
    k_eagg1<<<edgeGrid, 256>>>(g_h);                                      // 14
    k_post1<<<nodeWarpGrid, 256>>>(g_h, b2, out);                         // 15
}

// round 8
// speedup vs baseline: 14.6843x; 11.8023x over previous
#include <cuda_runtime.h>

#define NN 50000
#define EE 1600000
#define GRID 296          // 2 blocks/SM on 148+ SMs: co-residency guaranteed
#define NTHR 256
#define NWARP (GRID * NTHR / 32)

// ---------------- scratch (device globals) ----------------------------------
__device__ float g_h[NN * 64];
__device__ float g_agg[NN * 64];
__device__ float g_acc[NN * 64];
__device__ float g_asrc[NN * 4];
__device__ float g_adst[NN * 4];
__device__ float g_sum[NN * 4];
__device__ int   g_rowptr[NN + 1];
__device__ int   g_cursor[NN];
__device__ int   g_srcs[EE];
__device__ int   g_dsts[EE];
__device__ float g_stat[256];     // [0:128) raw stats, [128:192) scale, [192:256) shift
__device__ int   g_part[GRID];
__device__ int   g_partpre[GRID];
__device__ volatile int g_bar_count;
__device__ volatile int g_bar_gen;

__device__ __forceinline__ float neg_inf() { return __int_as_float(0xff800000); }
__device__ __forceinline__ float lrelu(float e) { return fmaxf(e, 0.2f * e); }

// ---------------- grid-wide barrier (all blocks co-resident) ----------------
__device__ __forceinline__ void gridsync() {
    __syncthreads();
    if (threadIdx.x == 0) {
        __threadfence();
        int gen = g_bar_gen;
        if (atomicAdd((int*)&g_bar_count, 1) == GRID - 1) {
            g_bar_count = 0;
            __threadfence();
            g_bar_gen = gen + 1;
        } else {
            while (g_bar_gen == gen) { }
        }
        __threadfence();
    }
    __syncthreads();
}

// ---------------- GEMM phase (tile loop) + fused alpha epilogue -------------
template <int K, int NO, bool BN, int H>
__device__ void gemm_phase(float* sm, const float* __restrict__ A,
                           const float* __restrict__ W, float* __restrict__ C,
                           const float* __restrict__ a_s, const float* __restrict__ a_d) {
    float (*As)[36] = (float(*)[36])sm;          // 64*36 = 2304 floats
    float (*Ws)[64] = (float(*)[64])(sm + 2304); // 32*64 = 2048 floats
    const int tid = threadIdx.x;
    const int ty = tid >> 4;
    const int tx = tid & 15;
    const int lr = tid >> 3;
    const int lc = (tid & 7) * 4;
    const int ntile = (NN + 63) / 64;

    for (int tile = blockIdx.x; tile < ntile; tile += GRID) {
        const int m0 = tile * 64;
        float acc[4][4] = {};
        for (int kt = 0; kt < K; kt += 32) {
            float4 sc, sh;
            if (BN) {
                sc = *reinterpret_cast<const float4*>(&g_stat[128 + kt + lc]);
                sh = *reinterpret_cast<const float4*>(&g_stat[192 + kt + lc]);
            }
#pragma unroll
            for (int rr = 0; rr < 64; rr += 32) {
                int row = m0 + lr + rr;
                float4 v = make_float4(0.f, 0.f, 0.f, 0.f);
                if (row < NN)
                    v = *reinterpret_cast<const float4*>(A + (size_t)row * K + kt + lc);
                if (BN) {
                    v.x = fmaxf(v.x * sc.x + sh.x, 0.f);
                    v.y = fmaxf(v.y * sc.y + sh.y, 0.f);
                    v.z = fmaxf(v.z * sc.z + sh.z, 0.f);
                    v.w = fmaxf(v.w * sc.w + sh.w, 0.f);
                }
                *reinterpret_cast<float4*>(&As[lr + rr][lc]) = v;
            }
#pragma unroll
            for (int kk = 0; kk < 32; kk += 16) {
                int k = ty + kk;
                int c = tx * 4;
                float4 v = make_float4(0.f, 0.f, 0.f, 0.f);
                if (NO == 64 || c < NO)
                    v = *reinterpret_cast<const float4*>(W + (size_t)(kt + k) * NO + c);
                *reinterpret_cast<float4*>(&Ws[k][c]) = v;
            }
            __syncthreads();
#pragma unroll
            for (int k = 0; k < 32; k++) {
                float a0 = As[ty * 4 + 0][k];
                float a1 = As[ty * 4 + 1][k];
                float a2 = As[ty * 4 + 2][k];
                float a3 = As[ty * 4 + 3][k];
                float4 b = *reinterpret_cast<const float4*>(&Ws[k][tx * 4]);
                acc[0][0] += a0 * b.x; acc[0][1] += a0 * b.y; acc[0][2] += a0 * b.z; acc[0][3] += a0 * b.w;
                acc[1][0] += a1 * b.x; acc[1][1] += a1 * b.y; acc[1][2] += a1 * b.z; acc[1][3] += a1 * b.w;
                acc[2][0] += a2 * b.x; acc[2][1] += a2 * b.y; acc[2][2] += a2 * b.z; acc[2][3] += a2 * b.w;
                acc[3][0] += a3 * b.x; acc[3][1] += a3 * b.y; acc[3][2] += a3 * b.z; acc[3][3] += a3 * b.w;
            }
            __syncthreads();
        }
#pragma unroll
        for (int i = 0; i < 4; i++) {
            int row = m0 + ty * 4 + i;
            if (row < NN && (NO == 64 || tx * 4 < NO)) {
                float4 v = make_float4(acc[i][0], acc[i][1], acc[i][2], acc[i][3]);
                *reinterpret_cast<float4*>(C + (size_t)row * NO + tx * 4) = v;
            }
        }
        const bool colok = (NO == 64) || (tx * 4 < NO);
        float4 av = make_float4(0.f, 0.f, 0.f, 0.f), dv = av;
        if (colok) {
            av = *reinterpret_cast<const float4*>(a_s + tx * 4);
            dv = *reinterpret_cast<const float4*>(a_d + tx * 4);
        }
#pragma unroll
        for (int i = 0; i < 4; i++) {
            float ps = acc[i][0] * av.x + acc[i][1] * av.y + acc[i][2] * av.z + acc[i][3] * av.w;
            float pd = acc[i][0] * dv.x + acc[i][1] * dv.y + acc[i][2] * dv.z + acc[i][3] * dv.w;
            ps += __shfl_xor_sync(0xffffffffu, ps, 1);
            pd += __shfl_xor_sync(0xffffffffu, pd, 1);
            ps += __shfl_xor_sync(0xffffffffu, ps, 2);
            pd += __shfl_xor_sync(0xffffffffu, pd, 2);
            int row = m0 + ty * 4 + i;
            if (H == 4) {
                if ((tx & 3) == 0 && row < NN) {
                    g_asrc[row * 4 + (tx >> 2)] = ps;
                    g_adst[row * 4 + (tx >> 2)] = pd;
                }
            } else {
                ps += __shfl_xor_sync(0xffffffffu, ps, 4);
                pd += __shfl_xor_sync(0xffffffffu, pd, 4);
                ps += __shfl_xor_sync(0xffffffffu, ps, 8);
                pd += __shfl_xor_sync(0xffffffffu, pd, 8);
                if (tx == 0 && row < NN) {
                    g_asrc[row] = ps;
                    g_adst[row] = pd;
                }
            }
        }
    }
}

// ---------------- edge-parallel aggregation phases ---------------------------
__device__ void eagg4_phase(const float* __restrict__ h) {
    const int lane = threadIdx.x & 31;
    const int warp0 = (blockIdx.x * NTHR + threadIdx.x) >> 5;
    const int c0 = lane, c1 = lane + 32;
    const bool hi = lane >= 16;
    const int h0 = hi ? 1 : 0;
    const int h1 = 2 + h0;

    for (int chunk = warp0; chunk < EE / 8; chunk += NWARP) {
        const int base = chunk * 8;
        int s[8], d[8];
#pragma unroll
        for (int j = 0; j < 8; j++) s[j] = g_srcs[base + j];
#pragma unroll
        for (int j = 0; j < 8; j++) d[j] = g_dsts[base + j];
        float w0[8], w1[8];
#pragma unroll
        for (int j = 0; j < 8; j++) {
            float4 av = *reinterpret_cast<const float4*>(&g_asrc[s[j] * 4]);
            float4 dv = *reinterpret_cast<const float4*>(&g_adst[d[j] * 4]);
            w0[j] = __expf(lrelu((hi ? av.y : av.x) + (hi ? dv.y : dv.x)));
            w1[j] = __expf(lrelu((hi ? av.w : av.z) + (hi ? dv.w : dv.z)));
        }
        float hv0[8], hv1[8];
#pragma unroll
        for (int j = 0; j < 8; j++) {
            hv0[j] = h[(size_t)s[j] * 64 + c0];
            hv1[j] = h[(size_t)s[j] * 64 + c1];
        }
        float acc0 = 0.f, acc1 = 0.f, ss0 = 0.f, ss1 = 0.f;
        int dcur = d[0];
#pragma unroll
        for (int j = 0; j < 8; j++) {
            if (d[j] != dcur) {
                atomicAdd(&g_acc[(size_t)dcur * 64 + c0], acc0);
                atomicAdd(&g_acc[(size_t)dcur * 64 + c1], acc1);
                if ((lane & 15) == 0) {
                    atomicAdd(&g_sum[dcur * 4 + h0], ss0);
                    atomicAdd(&g_sum[dcur * 4 + h1], ss1);
                }
                acc0 = acc1 = ss0 = ss1 = 0.f;
                dcur = d[j];
            }
            acc0 += w0[j] * hv0[j];
            acc1 += w1[j] * hv1[j];
            ss0 += w0[j];
            ss1 += w1[j];
        }
        atomicAdd(&g_acc[(size_t)dcur * 64 + c0], acc0);
        atomicAdd(&g_acc[(size_t)dcur * 64 + c1], acc1);
        if ((lane & 15) == 0) {
            atomicAdd(&g_sum[dcur * 4 + h0], ss0);
            atomicAdd(&g_sum[dcur * 4 + h1], ss1);
        }
    }
}

__device__ void eagg1_phase(const float* __restrict__ h) {
    const int lane = threadIdx.x & 31;
    const int warp0 = (blockIdx.x * NTHR + threadIdx.x) >> 5;
    const int c0 = lane, c1 = lane + 32;
    const bool use1 = lane < 8;

    for (int chunk = warp0; chunk < EE / 8; chunk += NWARP) {
        const int base = chunk * 8;
        int s[8], d[8];
#pragma unroll
        for (int j = 0; j < 8; j++) s[j] = g_srcs[base + j];
#pragma unroll
        for (int j = 0; j < 8; j++) d[j] = g_dsts[base + j];
        float w[8];
#pragma unroll
        for (int j = 0; j < 8; j++)
            w[j] = __expf(lrelu(g_asrc[s[j]] + g_adst[d[j]]));
        float hv0[8], hv1[8];
#pragma unroll
        for (int j = 0; j < 8; j++) {
            hv0[j] = h[(size_t)s[j] * 40 + c0];
            hv1[j] = use1 ? h[(size_t)s[j] * 40 + c1] : 0.f;
        }
        float acc0 = 0.f, acc1 = 0.f, ss = 0.f;
        int dcur = d[0];
#pragma unroll
        for (int j = 0; j < 8; j++) {
            if (d[j] != dcur) {
                atomicAdd(&g_acc[(size_t)dcur * 64 + c0], acc0);
                if (use1) atomicAdd(&g_acc[(size_t)dcur * 64 + c1], acc1);
                if (lane == 0) atomicAdd(&g_sum[dcur * 4], ss);
                acc0 = acc1 = ss = 0.f;
                dcur = d[j];
            }
            acc0 += w[j] * hv0[j];
            acc1 += w[j] * hv1[j];
            ss += w[j];
        }
        atomicAdd(&g_acc[(size_t)dcur * 64 + c0], acc0);
        if (use1) atomicAdd(&g_acc[(size_t)dcur * 64 + c1], acc1);
        if (lane == 0) atomicAdd(&g_sum[dcur * 4], ss);
    }
}

// ---------------- post phases ------------------------------------------------
// H=4: self-loop + normalize + bias; BN partial stats; zero g_acc inline.
__device__ void post4_phase(float* sm, const float* __restrict__ h,
                            const float* __restrict__ bias, float* __restrict__ out) {
    const int c = threadIdx.x & 63;   // constant per thread (stride % 64 == 0)
    const int head = c >> 4;
    const float bs = bias[c];
    float s_acc = 0.f, q_acc = 0.f;
    for (int idx = blockIdx.x * NTHR + threadIdx.x; idx < NN * 64; idx += GRID * NTHR) {
        int v = idx >> 6;
        float ws = __expf(lrelu(g_asrc[v * 4 + head] + g_adst[v * 4 + head]));
        float o = (g_acc[idx] + ws * h[idx]) / (g_sum[v * 4 + head] + ws + 1e-16f) + bs;
        out[idx] = o;
        g_acc[idx] = 0.f;     // safe: this thread is the only reader
        s_acc += o;
        q_acc += o * o;
    }
    float* shs = sm;
    float* shq = sm + 256;
    shs[threadIdx.x] = s_acc;
    shq[threadIdx.x] = q_acc;
    __syncthreads();
    if (threadIdx.x < 64) {
        float s = shs[threadIdx.x] + shs[threadIdx.x + 64] + shs[threadIdx.x + 128] + shs[threadIdx.x + 192];
        float q = shq[threadIdx.x] + shq[threadIdx.x + 64] + shq[threadIdx.x + 128] + shq[threadIdx.x + 192];
        atomicAdd(&g_stat[threadIdx.x], s);
        atomicAdd(&g_stat[64 + threadIdx.x], q);
    }
    __syncthreads();
}

// BN finalize (block 0) + everyone zeroes g_sum for the next layer.
__device__ void bnfinal_phase(const float* __restrict__ g, const float* __restrict__ beta) {
    if (blockIdx.x == 0 && threadIdx.x < 64) {
        int c = threadIdx.x;
        float mean = g_stat[c] * (1.0f / NN);
        float var = g_stat[64 + c] * (1.0f / NN) - mean * mean;
        float sc = g[c] * rsqrtf(var + 1e-5f);
        g_stat[128 + c] = sc;
        g_stat[192 + c] = beta[c] - mean * sc;
        g_stat[c] = 0.f;
        g_stat[64 + c] = 0.f;
    }
    for (int i = blockIdx.x * NTHR + threadIdx.x; i < NN * 4; i += GRID * NTHR)
        g_sum[i] = 0.f;
}

// H=1: self-loop + normalize + bias + log-softmax (warp per node).
__device__ void post1_phase(const float* __restrict__ h, const float* __restrict__ bias,
                            float* __restrict__ out) {
    const int lane = threadIdx.x & 31;
    const int warp0 = (blockIdx.x * NTHR + threadIdx.x) >> 5;
    const int c0 = lane, c1 = lane + 32;
    const bool use1 = lane < 8;
    for (int gw = warp0; gw < NN; gw += NWARP) {
        float ws = __expf(lrelu(g_asrc[gw] + g_adst[gw]));
        float inv = 1.f / (g_sum[gw * 4] + ws + 1e-16f);
        float a0 = g_acc[(size_t)gw * 64 + c0];
        float a1 = use1 ? g_acc[(size_t)gw * 64 + c1] : 0.f;
        float o0 = (a0 + ws * h[(size_t)gw * 40 + c0]) * inv + bias[c0];
        float o1 = use1 ? ((a1 + ws * h[(size_t)gw * 40 + c1]) * inv + bias[c1]) : neg_inf();
        float m = fmaxf(o0, o1);
#pragma unroll
        for (int off = 16; off; off >>= 1) m = fmaxf(m, __shfl_xor_sync(0xffffffffu, m, off));
        float se = __expf(o0 - m) + (use1 ? __expf(o1 - m) : 0.f);
#pragma unroll
        for (int off = 16; off; off >>= 1) se += __shfl_xor_sync(0xffffffffu, se, off);
        float ls = __logf(se);
        out[(size_t)gw * 40 + c0] = o0 - m - ls;
        if (use1) out[(size_t)gw * 40 + c1] = o1 - m - ls;
    }
}

// ---------------- THE mega-kernel --------------------------------------------
__global__ __launch_bounds__(NTHR, 2) void k_mega(
    const float* __restrict__ x, const int* __restrict__ ei,
    const float* __restrict__ W0, const float* __restrict__ as0, const float* __restrict__ ad0,
    const float* __restrict__ b0, const float* __restrict__ g0, const float* __restrict__ be0,
    const float* __restrict__ W1, const float* __restrict__ as1, const float* __restrict__ ad1,
    const float* __restrict__ b1, const float* __restrict__ g1, const float* __restrict__ be1,
    const float* __restrict__ W2, const float* __restrict__ as2, const float* __restrict__ ad2,
    const float* __restrict__ b2, float* __restrict__ out) {
    __shared__ float smbuf[4480];
    const int tid = threadIdx.x;
    const int gt = blockIdx.x * NTHR + tid;

    // P0: zero all scratch (no cross-launch invariants)
    for (int i = gt; i < NN * 64; i += GRID * NTHR) g_acc[i] = 0.f;
    for (int i = gt; i < NN * 4; i += GRID * NTHR) g_sum[i] = 0.f;
    for (int i = gt; i < NN; i += GRID * NTHR) g_cursor[i] = 0;
    if (gt < 128) g_stat[gt] = 0.f;
    gridsync();

    // P1: count in-degrees
    for (int e = gt; e < EE; e += GRID * NTHR)
        atomicAdd(&g_cursor[ei[EE + e]], 1);
    gridsync();

    // P2: per-block local exclusive scan of counts
    const int CH = (NN + GRID - 1) / GRID;   // 170
    const int start = blockIdx.x * CH;
    int* si = (int*)smbuf;                   // [0 .. CH]
    for (int i = tid; i < CH; i += NTHR)
        si[i] = (start + i < NN) ? g_cursor[start + i] : 0;
    __syncthreads();
    if (tid == 0) {
        int run = 0;
        for (int i = 0; i < CH; i++) { int v = si[i]; si[i] = run; run += v; }
        si[CH] = run;
        g_part[blockIdx.x] = run;
    }
    __syncthreads();
    gridsync();

    // P3: block 0 scans block totals
    if (blockIdx.x == 0) {
        int* sp = (int*)(smbuf + 2304);
        for (int i = tid; i < GRID; i += NTHR) sp[i] = g_part[i];
        __syncthreads();
        if (tid == 0) {
            int run = 0;
            for (int i = 0; i < GRID; i++) { int v = sp[i]; sp[i] = run; run += v; }
        }
        __syncthreads();
        for (int i = tid; i < GRID; i += NTHR) g_partpre[i] = sp[i];
    }
    gridsync();

    // P4: write rowptr + scatter cursors
    {
        const int base = g_partpre[blockIdx.x];
        for (int i = tid; i < CH; i += NTHR) {
            int v = start + i;
            if (v < NN) {
                int rp = base + si[i];
                g_rowptr[v] = rp;
                g_cursor[v] = rp;
            }
        }
        if (blockIdx.x == 0 && tid == 0) g_rowptr[NN] = EE;
    }
    gridsync();

    // P5: scatter edges into CSR (dst-sorted)
    for (int e = gt; e < EE; e += GRID * NTHR) {
        int s = ei[e];
        int d = ei[EE + e];
        int pos = atomicAdd(&g_cursor[d], 1);
        g_srcs[pos] = s;
        g_dsts[pos] = d;
    }
    gridsync();

    // ---- layer 0 ----
    gemm_phase<128, 64, false, 4>(smbuf, x, W0, g_h, as0, ad0);
    gridsync();
    eagg4_phase(g_h);
    gridsync();
    post4_phase(smbuf, g_h, b0, g_agg);
    gridsync();
    bnfinal_phase(g0, be0);
    gridsync();

    // ---- layer 1 ----
    gemm_phase<64, 64, true, 4>(smbuf, g_agg, W1, g_h, as1, ad1);
    gridsync();
    eagg4_phase(g_h);
    gridsync();
    post4_phase(smbuf, g_h, b1, g_agg);
    gridsync();
    bnfinal_phase(g1, be1);
    gridsync();

    // ---- layer 2 ----
    gemm_phase<64, 40, true, 1>(smbuf, g_agg, W2, g_h, as2, ad2);
    gridsync();
    eagg1_phase(g_h);
    gridsync();
    post1_phase(g_h, b2, out);
}

// ---------------- launch ------------------------------------------------------
extern "C" void kernel_launch(void* const* d_in, const int* in_sizes, int n_in,
                              void* d_out, int out_size) {
    const float* x   = (const float*)d_in[0];
    const int*   ei  = (const int*)d_in[1];
    const float* W0  = (const float*)d_in[2];
    const float* as0 = (const float*)d_in[3];
    const float* ad0 = (const float*)d_in[4];
    const float* b0  = (const float*)d_in[5];
    const float* g0  = (const float*)d_in[6];
    const float* be0 = (const float*)d_in[7];
    const float* W1  = (const float*)d_in[8];
    const float* as1 = (const float*)d_in[9];
    const float* ad1 = (const float*)d_in[10];
    const float* b1  = (const float*)d_in[11];
    const float* g1  = (const float*)d_in[12];
    const float* be1 = (const float*)d_in[13];
    const float* W2  = (const float*)d_in[14];
    const float* as2 = (const float*)d_in[15];
    const float* ad2 = (const float*)d_in[16];
    const float* b2  = (const float*)d_in[17];
    float* out = (float*)d_out;

    k_mega<<<GRID, NTHR>>>(x, ei, W0, as0, ad0, b0, g0, be0,
                           W1, as1, ad1, b1, g1, be1,
                           W2, as2, ad2, b2, out);
}

// round 9
// speedup vs baseline: 16.6546x; 1.1342x over previous
#include <cuda_runtime.h>

#define NN 50000
#define EE 1600000
#define GRID 592          // 4 blocks/SM × 148 SMs (GB300 has 152: capacity 608 ≥ 592)
#define NTHR 256
#define NWARP (GRID * NTHR / 32)

// ---------------- scratch (device globals) ----------------------------------
__device__ float g_h[NN * 64];
__device__ float g_agg[NN * 64];
__device__ float g_acc[NN * 64];
__device__ float g_asrc[NN * 4];
__device__ float g_adst[NN * 4];
__device__ float g_sum[NN * 4];
__device__ int   g_rowptr[NN + 1];
__device__ int   g_cursor[NN];
__device__ int   g_srcs[EE];
__device__ int   g_dsts[EE];
__device__ float g_stat[256];     // [0:128) raw stats, [128:192) scale, [192:256) shift
__device__ int   g_part[GRID];
__device__ int   g_partpre[GRID];
__device__ volatile int g_bar_count;
__device__ volatile int g_bar_gen;

__device__ __forceinline__ float neg_inf() { return __int_as_float(0xff800000); }
__device__ __forceinline__ float lrelu(float e) { return fmaxf(e, 0.2f * e); }

// ---------------- grid-wide barrier (all blocks co-resident) ----------------
__device__ __forceinline__ void gridsync() {
    __syncthreads();
    if (threadIdx.x == 0) {
        __threadfence();
        int gen = g_bar_gen;
        if (atomicAdd((int*)&g_bar_count, 1) == GRID - 1) {
            g_bar_count = 0;
            __threadfence();
            g_bar_gen = gen + 1;
        } else {
            while (g_bar_gen == gen) { }
        }
        __threadfence();
    }
    __syncthreads();
}

// ---------------- GEMM phase (tile loop) + fused alpha epilogue -------------
template <int K, int NO, bool BN, int H>
__device__ void gemm_phase(float* sm, const float* __restrict__ A,
                           const float* __restrict__ W, float* __restrict__ C,
                           const float* __restrict__ a_s, const float* __restrict__ a_d) {
    float (*As)[36] = (float(*)[36])sm;          // 64*36 = 2304 floats
    float (*Ws)[64] = (float(*)[64])(sm + 2304); // 32*64 = 2048 floats
    const int tid = threadIdx.x;
    const int ty = tid >> 4;
    const int tx = tid & 15;
    const int lr = tid >> 3;
    const int lc = (tid & 7) * 4;
    const int ntile = (NN + 63) / 64;

    for (int tile = blockIdx.x; tile < ntile; tile += GRID) {
        const int m0 = tile * 64;
        float acc[4][4] = {};
        for (int kt = 0; kt < K; kt += 32) {
            float4 sc, sh;
            if (BN) {
                sc = *reinterpret_cast<const float4*>(&g_stat[128 + kt + lc]);
                sh = *reinterpret_cast<const float4*>(&g_stat[192 + kt + lc]);
            }
#pragma unroll
            for (int rr = 0; rr < 64; rr += 32) {
                int row = m0 + lr + rr;
                float4 v = make_float4(0.f, 0.f, 0.f, 0.f);
                if (row < NN)
                    v = *reinterpret_cast<const float4*>(A + (size_t)row * K + kt + lc);
                if (BN) {
                    v.x = fmaxf(v.x * sc.x + sh.x, 0.f);
                    v.y = fmaxf(v.y * sc.y + sh.y, 0.f);
                    v.z = fmaxf(v.z * sc.z + sh.z, 0.f);
                    v.w = fmaxf(v.w * sc.w + sh.w, 0.f);
                }
                *reinterpret_cast<float4*>(&As[lr + rr][lc]) = v;
            }
#pragma unroll
            for (int kk = 0; kk < 32; kk += 16) {
                int k = ty + kk;
                int c = tx * 4;
                float4 v = make_float4(0.f, 0.f, 0.f, 0.f);
                if (NO == 64 || c < NO)
                    v = *reinterpret_cast<const float4*>(W + (size_t)(kt + k) * NO + c);
                *reinterpret_cast<float4*>(&Ws[k][c]) = v;
            }
            __syncthreads();
#pragma unroll
            for (int k = 0; k < 32; k++) {
                float a0 = As[ty * 4 + 0][k];
                float a1 = As[ty * 4 + 1][k];
                float a2 = As[ty * 4 + 2][k];
                float a3 = As[ty * 4 + 3][k];
                float4 b = *reinterpret_cast<const float4*>(&Ws[k][tx * 4]);
                acc[0][0] += a0 * b.x; acc[0][1] += a0 * b.y; acc[0][2] += a0 * b.z; acc[0][3] += a0 * b.w;
                acc[1][0] += a1 * b.x; acc[1][1] += a1 * b.y; acc[1][2] += a1 * b.z; acc[1][3] += a1 * b.w;
                acc[2][0] += a2 * b.x; acc[2][1] += a2 * b.y; acc[2][2] += a2 * b.z; acc[2][3] += a2 * b.w;
                acc[3][0] += a3 * b.x; acc[3][1] += a3 * b.y; acc[3][2] += a3 * b.z; acc[3][3] += a3 * b.w;
            }
            __syncthreads();
        }
#pragma unroll
        for (int i = 0; i < 4; i++) {
            int row = m0 + ty * 4 + i;
            if (row < NN && (NO == 64 || tx * 4 < NO)) {
                float4 v = make_float4(acc[i][0], acc[i][1], acc[i][2], acc[i][3]);
                *reinterpret_cast<float4*>(C + (size_t)row * NO + tx * 4) = v;
            }
        }
        const bool colok = (NO == 64) || (tx * 4 < NO);
        float4 av = make_float4(0.f, 0.f, 0.f, 0.f), dv = av;
        if (colok) {
            av = *reinterpret_cast<const float4*>(a_s + tx * 4);
            dv = *reinterpret_cast<const float4*>(a_d + tx * 4);
        }
#pragma unroll
        for (int i = 0; i < 4; i++) {
            float ps = acc[i][0] * av.x + acc[i][1] * av.y + acc[i][2] * av.z + acc[i][3] * av.w;
            float pd = acc[i][0] * dv.x + acc[i][1] * dv.y + acc[i][2] * dv.z + acc[i][3] * dv.w;
            ps += __shfl_xor_sync(0xffffffffu, ps, 1);
            pd += __shfl_xor_sync(0xffffffffu, pd, 1);
            ps += __shfl_xor_sync(0xffffffffu, ps, 2);
            pd += __shfl_xor_sync(0xffffffffu, pd, 2);
            int row = m0 + ty * 4 + i;
            if (H == 4) {
                if ((tx & 3) == 0 && row < NN) {
                    g_asrc[row * 4 + (tx >> 2)] = ps;
                    g_adst[row * 4 + (tx >> 2)] = pd;
                }
            } else {
                ps += __shfl_xor_sync(0xffffffffu, ps, 4);
                pd += __shfl_xor_sync(0xffffffffu, pd, 4);
                ps += __shfl_xor_sync(0xffffffffu, ps, 8);
                pd += __shfl_xor_sync(0xffffffffu, pd, 8);
                if (tx == 0 && row < NN) {
                    g_asrc[row] = ps;
                    g_adst[row] = pd;
                }
            }
        }
    }
}

// ---------------- edge-parallel aggregation phases ---------------------------
// 8-edge chunks for src/dst (flush rate unchanged); float batches in 4-edge
// halves to stay under the 64-register cap (4 blocks/SM occupancy).
__device__ void eagg4_phase(const float* __restrict__ h) {
    const int lane = threadIdx.x & 31;
    const int warp0 = (blockIdx.x * NTHR + threadIdx.x) >> 5;
    const int c0 = lane, c1 = lane + 32;
    const bool hi = lane >= 16;
    const int h0 = hi ? 1 : 0;
    const int h1 = 2 + h0;

    for (int chunk = warp0; chunk < EE / 8; chunk += NWARP) {
        const int base = chunk * 8;
        int s[8], d[8];
#pragma unroll
        for (int j = 0; j < 8; j++) s[j] = g_srcs[base + j];
#pragma unroll
        for (int j = 0; j < 8; j++) d[j] = g_dsts[base + j];

        float acc0 = 0.f, acc1 = 0.f, ss0 = 0.f, ss1 = 0.f;
        int dcur = d[0];
#pragma unroll
        for (int half = 0; half < 2; half++) {
            const int o = half * 4;
            float w0[4], w1[4], hv0[4], hv1[4];
#pragma unroll
            for (int j = 0; j < 4; j++) {
                float4 av = *reinterpret_cast<const float4*>(&g_asrc[s[o + j] * 4]);
                float4 dv = *reinterpret_cast<const float4*>(&g_adst[d[o + j] * 4]);
                w0[j] = __expf(lrelu((hi ? av.y : av.x) + (hi ? dv.y : dv.x)));
                w1[j] = __expf(lrelu((hi ? av.w : av.z) + (hi ? dv.w : dv.z)));
            }
#pragma unroll
            for (int j = 0; j < 4; j++) {
                hv0[j] = h[(size_t)s[o + j] * 64 + c0];
                hv1[j] = h[(size_t)s[o + j] * 64 + c1];
            }
#pragma unroll
            for (int j = 0; j < 4; j++) {
                if (d[o + j] != dcur) {
                    atomicAdd(&g_acc[(size_t)dcur * 64 + c0], acc0);
                    atomicAdd(&g_acc[(size_t)dcur * 64 + c1], acc1);
                    if ((lane & 15) == 0) {
                        atomicAdd(&g_sum[dcur * 4 + h0], ss0);
                        atomicAdd(&g_sum[dcur * 4 + h1], ss1);
                    }
                    acc0 = acc1 = ss0 = ss1 = 0.f;
                    dcur = d[o + j];
                }
                acc0 += w0[j] * hv0[j];
                acc1 += w1[j] * hv1[j];
                ss0 += w0[j];
                ss1 += w1[j];
            }
        }
        atomicAdd(&g_acc[(size_t)dcur * 64 + c0], acc0);
        atomicAdd(&g_acc[(size_t)dcur * 64 + c1], acc1);
        if ((lane & 15) == 0) {
            atomicAdd(&g_sum[dcur * 4 + h0], ss0);
            atomicAdd(&g_sum[dcur * 4 + h1], ss1);
        }
    }
}

__device__ void eagg1_phase(const float* __restrict__ h) {
    const int lane = threadIdx.x & 31;
    const int warp0 = (blockIdx.x * NTHR + threadIdx.x) >> 5;
    const int c0 = lane, c1 = lane + 32;
    const bool use1 = lane < 8;

    for (int chunk = warp0; chunk < EE / 8; chunk += NWARP) {
        const int base = chunk * 8;
        int s[8], d[8];
#pragma unroll
        for (int j = 0; j < 8; j++) s[j] = g_srcs[base + j];
#pragma unroll
        for (int j = 0; j < 8; j++) d[j] = g_dsts[base + j];

        float acc0 = 0.f, acc1 = 0.f, ss = 0.f;
        int dcur = d[0];
#pragma unroll
        for (int half = 0; half < 2; half++) {
            const int o = half * 4;
            float w[4], hv0[4], hv1[4];
#pragma unroll
            for (int j = 0; j < 4; j++)
                w[j] = __expf(lrelu(g_asrc[s[o + j]] + g_adst[d[o + j]]));
#pragma unroll
            for (int j = 0; j < 4; j++) {
                hv0[j] = h[(size_t)s[o + j] * 40 + c0];
                hv1[j] = use1 ? h[(size_t)s[o + j] * 40 + c1] : 0.f;
            }
#pragma unroll
            for (int j = 0; j < 4; j++) {
                if (d[o + j] != dcur) {
                    atomicAdd(&g_acc[(size_t)dcur * 64 + c0], acc0);
                    if (use1) atomicAdd(&g_acc[(size_t)dcur * 64 + c1], acc1);
                    if (lane == 0) atomicAdd(&g_sum[dcur * 4], ss);
                    acc0 = acc1 = ss = 0.f;
                    dcur = d[o + j];
                }
                acc0 += w[j] * hv0[j];
                acc1 += w[j] * hv1[j];
                ss += w[j];
            }
        }
        atomicAdd(&g_acc[(size_t)dcur * 64 + c0], acc0);
        if (use1) atomicAdd(&g_acc[(size_t)dcur * 64 + c1], acc1);
        if (lane == 0) atomicAdd(&g_sum[dcur * 4], ss);
    }
}

// ---------------- post phases ------------------------------------------------
__device__ void post4_phase(float* sm, const float* __restrict__ h,
                            const float* __restrict__ bias, float* __restrict__ out) {
    const int c = threadIdx.x & 63;   // constant per thread (stride % 64 == 0)
    const int head = c >> 4;
    const float bs = bias[c];
    float s_acc = 0.f, q_acc = 0.f;
    for (int idx = blockIdx.x * NTHR + threadIdx.x; idx < NN * 64; idx += GRID * NTHR) {
        int v = idx >> 6;
        float ws = __expf(lrelu(g_asrc[v * 4 + head] + g_adst[v * 4 + head]));
        float o = (g_acc[idx] + ws * h[idx]) / (g_sum[v * 4 + head] + ws + 1e-16f) + bs;
        out[idx] = o;
        g_acc[idx] = 0.f;     // safe: this thread is the only reader
        s_acc += o;
        q_acc += o * o;
    }
    float* shs = sm;
    float* shq = sm + 256;
    shs[threadIdx.x] = s_acc;
    shq[threadIdx.x] = q_acc;
    __syncthreads();
    if (threadIdx.x < 64) {
        float s = shs[threadIdx.x] + shs[threadIdx.x + 64] + shs[threadIdx.x + 128] + shs[threadIdx.x + 192];
        float q = shq[threadIdx.x] + shq[threadIdx.x + 64] + shq[threadIdx.x + 128] + shq[threadIdx.x + 192];
        atomicAdd(&g_stat[threadIdx.x], s);
        atomicAdd(&g_stat[64 + threadIdx.x], q);
    }
    __syncthreads();
}

__device__ void bnfinal_phase(const float* __restrict__ g, const float* __restrict__ beta) {
    if (blockIdx.x == 0 && threadIdx.x < 64) {
        int c = threadIdx.x;
        float mean = g_stat[c] * (1.0f / NN);
        float var = g_stat[64 + c] * (1.0f / NN) - mean * mean;
        float sc = g[c] * rsqrtf(var + 1e-5f);
        g_stat[128 + c] = sc;
        g_stat[192 + c] = beta[c] - mean * sc;
        g_stat[c] = 0.f;
        g_stat[64 + c] = 0.f;
    }
    float4 z = make_float4(0.f, 0.f, 0.f, 0.f);
    float4* s4 = reinterpret_cast<float4*>(g_sum);
    for (int i = blockIdx.x * NTHR + threadIdx.x; i < NN; i += GRID * NTHR)
        s4[i] = z;
}

__device__ void post1_phase(const float* __restrict__ h, const float* __restrict__ bias,
                            float* __restrict__ out) {
    const int lane = threadIdx.x & 31;
    const int warp0 = (blockIdx.x * NTHR + threadIdx.x) >> 5;
    const int c0 = lane, c1 = lane + 32;
    const bool use1 = lane < 8;
    for (int gw = warp0; gw < NN; gw += NWARP) {
        float ws = __expf(lrelu(g_asrc[gw] + g_adst[gw]));
        float inv = 1.f / (g_sum[gw * 4] + ws + 1e-16f);
        float a0 = g_acc[(size_t)gw * 64 + c0];
        float a1 = use1 ? g_acc[(size_t)gw * 64 + c1] : 0.f;
        float o0 = (a0 + ws * h[(size_t)gw * 40 + c0]) * inv + bias[c0];
        float o1 = use1 ? ((a1 + ws * h[(size_t)gw * 40 + c1]) * inv + bias[c1]) : neg_inf();
        float m = fmaxf(o0, o1);
#pragma unroll
        for (int off = 16; off; off >>= 1) m = fmaxf(m, __shfl_xor_sync(0xffffffffu, m, off));
        float se = __expf(o0 - m) + (use1 ? __expf(o1 - m) : 0.f);
#pragma unroll
        for (int off = 16; off; off >>= 1) se += __shfl_xor_sync(0xffffffffu, se, off);
        float ls = __logf(se);
        out[(size_t)gw * 40 + c0] = o0 - m - ls;
        if (use1) out[(size_t)gw * 40 + c1] = o1 - m - ls;
    }
}

// ---------------- THE mega-kernel --------------------------------------------
__global__ __launch_bounds__(NTHR, 4) void k_mega(
    const float* __restrict__ x, const int* __restrict__ ei,
    const float* __restrict__ W0, const float* __restrict__ as0, const float* __restrict__ ad0,
    const float* __restrict__ b0, const float* __restrict__ g0, const float* __restrict__ be0,
    const float* __restrict__ W1, const float* __restrict__ as1, const float* __restrict__ ad1,
    const float* __restrict__ b1, const float* __restrict__ g1, const float* __restrict__ be1,
    const float* __restrict__ W2, const float* __restrict__ as2, const float* __restrict__ ad2,
    const float* __restrict__ b2, float* __restrict__ out) {
    __shared__ float smbuf[4480];
    const int tid = threadIdx.x;
    const int gt = blockIdx.x * NTHR + tid;

    // P0: zero all scratch (vectorized)
    {
        float4 z = make_float4(0.f, 0.f, 0.f, 0.f);
        float4* a4 = reinterpret_cast<float4*>(g_acc);
        for (int i = gt; i < NN * 16; i += GRID * NTHR) a4[i] = z;
        float4* s4 = reinterpret_cast<float4*>(g_sum);
        for (int i = gt; i < NN; i += GRID * NTHR) s4[i] = z;
        for (int i = gt; i < NN; i += GRID * NTHR) g_cursor[i] = 0;
        if (gt < 128) g_stat[gt] = 0.f;
    }
    gridsync();

    // P1: count in-degrees
    for (int e = gt; e < EE; e += GRID * NTHR)
        atomicAdd(&g_cursor[ei[EE + e]], 1);
    gridsync();

    // P2: per-block local exclusive scan of counts
    const int CH = (NN + GRID - 1) / GRID;   // 85
    const int start = blockIdx.x * CH;
    int* si = (int*)smbuf;                   // [0 .. CH]
    for (int i = tid; i < CH; i += NTHR)
        si[i] = (start + i < NN) ? g_cursor[start + i] : 0;
    __syncthreads();
    if (tid == 0) {
        int run = 0;
        for (int i = 0; i < CH; i++) { int v = si[i]; si[i] = run; run += v; }
        si[CH] = run;
        g_part[blockIdx.x] = run;
    }
    __syncthreads();
    gridsync();

    // P3: block 0 scans block totals
    if (blockIdx.x == 0) {
        int* sp = (int*)(smbuf + 2304);      // 592 ints fits (2304+592 < 4480)
        for (int i = tid; i < GRID; i += NTHR) sp[i] = g_part[i];
        __syncthreads();
        if (tid == 0) {
            int run = 0;
            for (int i = 0; i < GRID; i++) { int v = sp[i]; sp[i] = run; run += v; }
        }
        __syncthreads();
        for (int i = tid; i < GRID; i += NTHR) g_partpre[i] = sp[i];
    }
    gridsync();

    // P4: write rowptr + scatter cursors
    {
        const int base = g_partpre[blockIdx.x];
        for (int i = tid; i < CH; i += NTHR) {
            int v = start + i;
            if (v < NN) {
                int rp = base + si[i];
                g_rowptr[v] = rp;
                g_cursor[v] = rp;
            }
        }
        if (blockIdx.x == 0 && tid == 0) g_rowptr[NN] = EE;
    }
    gridsync();

    // P5: scatter edges into CSR (dst-sorted)
    for (int e = gt; e < EE; e += GRID * NTHR) {
        int s = ei[e];
        int d = ei[EE + e];
        int pos = atomicAdd(&g_cursor[d], 1);
        g_srcs[pos] = s;
        g_dsts[pos] = d;
    }
    gridsync();

    // ---- layer 0 ----
    gemm_phase<128, 64, false, 4>(smbuf, x, W0, g_h, as0, ad0);
    gridsync();
    eagg4_phase(g_h);
    gridsync();
    post4_phase(smbuf, g_h, b0, g_agg);
    gridsync();
    bnfinal_phase(g0, be0);
    gridsync();

    // ---- layer 1 ----
    gemm_phase<64, 64, true, 4>(smbuf, g_agg, W1, g_h, as1, ad1);
    gridsync();
    eagg4_phase(g_h);
    gridsync();
    post4_phase(smbuf, g_h, b1, g_agg);
    gridsync();
    bnfinal_phase(g1, be1);
    gridsync();

    // ---- layer 2 ----
    gemm_phase<64, 40, true, 1>(smbuf, g_agg, W2, g_h, as2, ad2);
    gridsync();
    eagg1_phase(g_h);
    gridsync();
    post1_phase(g_h, b2, out);
}

// ---------------- launch ------------------------------------------------------
extern "C" void kernel_launch(void* const* d_in, const int* in_sizes, int n_in,
                              void* d_out, int out_size) {
    const float* x   = (const float*)d_in[0];
    const int*   ei  = (const int*)d_in[1];
    const float* W0  = (const float*)d_in[2];
    const float* as0 = (const float*)d_in[3];
    const float* ad0 = (const float*)d_in[4];
    const float* b0  = (const float*)d_in[5];
    const float* g0  = (const float*)d_in[6];
    const float* be0 = (const float*)d_in[7];
    const float* W1  = (const float*)d_in[8];
    const float* as1 = (const float*)d_in[9];
    const float* ad1 = (const float*)d_in[10];
    const float* b1  = (const float*)d_in[11];
    const float* g1  = (const float*)d_in[12];
    const float* be1 = (const float*)d_in[13];
    const float* W2  = (const float*)d_in[14];
    const float* as2 = (const float*)d_in[15];
    const float* ad2 = (const float*)d_in[16];
    const float* b2  = (const float*)d_in[17];
    float* out = (float*)d_out;

    k_mega<<<GRID, NTHR>>>(x, ei, W0, as0, ad0, b0, g0, be0,
                           W1, as1, ad1, b1, g1, be1,
                           W2, as2, ad2, b2, out);
}

// round 10
// speedup vs baseline: 19.5012x; 1.1709x over previous
#include <cuda_runtime.h>

#define NN 50000
#define EE 1600000
#define GRID 592          // 4 blocks/SM × 148 SMs (GB300 has 152: capacity 608 ≥ 592)
#define NTHR 256
#define NWARP (GRID * NTHR / 32)   // 4736
#define EPW 344                    // edges per warp (mult of 8; 344*4736 ≥ EE)

// ---------------- scratch (device globals) ----------------------------------
__device__ float g_h[NN * 64];
__device__ float g_agg[NN * 64];
__device__ float g_acc[NN * 64];
__device__ float g_w[(size_t)EE * 4];   // per-edge per-head softmax numerators
__device__ float g_asrc[NN * 4];
__device__ float g_adst[NN * 4];
__device__ float g_sum[NN * 4];
__device__ int   g_rowptr[NN + 1];
__device__ int   g_cursor[NN];
__device__ int   g_srcs[EE];
__device__ int   g_dsts[EE];
__device__ float g_stat[256];     // [0:128) raw stats, [128:192) scale, [192:256) shift
__device__ int   g_part[GRID];
__device__ int   g_partpre[GRID];
__device__ volatile int g_bar_count;
__device__ volatile int g_bar_gen;

__device__ __forceinline__ float neg_inf() { return __int_as_float(0xff800000); }
__device__ __forceinline__ float lrelu(float e) { return fmaxf(e, 0.2f * e); }

// ---------------- grid-wide barrier (all blocks co-resident) ----------------
__device__ __forceinline__ void gridsync() {
    __syncthreads();
    if (threadIdx.x == 0) {
        __threadfence();
        int gen = g_bar_gen;
        if (atomicAdd((int*)&g_bar_count, 1) == GRID - 1) {
            g_bar_count = 0;
            __threadfence();
            g_bar_gen = gen + 1;
        } else {
            while (g_bar_gen == gen) { }
        }
        __threadfence();
    }
    __syncthreads();
}

// ---------------- GEMM phase (tile loop) + fused alpha epilogue -------------
template <int K, int NO, bool BN, int H>
__device__ void gemm_phase(float* sm, const float* __restrict__ A,
                           const float* __restrict__ W, float* __restrict__ C,
                           const float* __restrict__ a_s, const float* __restrict__ a_d) {
    float (*As)[36] = (float(*)[36])sm;          // 64*36 = 2304 floats
    float (*Ws)[64] = (float(*)[64])(sm + 2304); // 32*64 = 2048 floats
    const int tid = threadIdx.x;
    const int ty = tid >> 4;
    const int tx = tid & 15;
    const int lr = tid >> 3;
    const int lc = (tid & 7) * 4;
    const int ntile = (NN + 63) / 64;

    for (int tile = blockIdx.x; tile < ntile; tile += GRID) {
        const int m0 = tile * 64;
        float acc[4][4] = {};
        for (int kt = 0; kt < K; kt += 32) {
            float4 sc, sh;
            if (BN) {
                sc = *reinterpret_cast<const float4*>(&g_stat[128 + kt + lc]);
                sh = *reinterpret_cast<const float4*>(&g_stat[192 + kt + lc]);
            }
#pragma unroll
            for (int rr = 0; rr < 64; rr += 32) {
                int row = m0 + lr + rr;
                float4 v = make_float4(0.f, 0.f, 0.f, 0.f);
                if (row < NN)
                    v = *reinterpret_cast<const float4*>(A + (size_t)row * K + kt + lc);
                if (BN) {
                    v.x = fmaxf(v.x * sc.x + sh.x, 0.f);
                    v.y = fmaxf(v.y * sc.y + sh.y, 0.f);
                    v.z = fmaxf(v.z * sc.z + sh.z, 0.f);
                    v.w = fmaxf(v.w * sc.w + sh.w, 0.f);
                }
                *reinterpret_cast<float4*>(&As[lr + rr][lc]) = v;
            }
#pragma unroll
            for (int kk = 0; kk < 32; kk += 16) {
                int k = ty + kk;
                int c = tx * 4;
                float4 v = make_float4(0.f, 0.f, 0.f, 0.f);
                if (NO == 64 || c < NO)
                    v = *reinterpret_cast<const float4*>(W + (size_t)(kt + k) * NO + c);
                *reinterpret_cast<float4*>(&Ws[k][c]) = v;
            }
            __syncthreads();
#pragma unroll
            for (int k = 0; k < 32; k++) {
                float a0 = As[ty * 4 + 0][k];
                float a1 = As[ty * 4 + 1][k];
                float a2 = As[ty * 4 + 2][k];
                float a3 = As[ty * 4 + 3][k];
                float4 b = *reinterpret_cast<const float4*>(&Ws[k][tx * 4]);
                acc[0][0] += a0 * b.x; acc[0][1] += a0 * b.y; acc[0][2] += a0 * b.z; acc[0][3] += a0 * b.w;
                acc[1][0] += a1 * b.x; acc[1][1] += a1 * b.y; acc[1][2] += a1 * b.z; acc[1][3] += a1 * b.w;
                acc[2][0] += a2 * b.x; acc[2][1] += a2 * b.y; acc[2][2] += a2 * b.z; acc[2][3] += a2 * b.w;
                acc[3][0] += a3 * b.x; acc[3][1] += a3 * b.y; acc[3][2] += a3 * b.z; acc[3][3] += a3 * b.w;
            }
            __syncthreads();
        }
#pragma unroll
        for (int i = 0; i < 4; i++) {
            int row = m0 + ty * 4 + i;
            if (row < NN && (NO == 64 || tx * 4 < NO)) {
                float4 v = make_float4(acc[i][0], acc[i][1], acc[i][2], acc[i][3]);
                *reinterpret_cast<float4*>(C + (size_t)row * NO + tx * 4) = v;
            }
        }
        const bool colok = (NO == 64) || (tx * 4 < NO);
        float4 av = make_float4(0.f, 0.f, 0.f, 0.f), dv = av;
        if (colok) {
            av = *reinterpret_cast<const float4*>(a_s + tx * 4);
            dv = *reinterpret_cast<const float4*>(a_d + tx * 4);
        }
#pragma unroll
        for (int i = 0; i < 4; i++) {
            float ps = acc[i][0] * av.x + acc[i][1] * av.y + acc[i][2] * av.z + acc[i][3] * av.w;
            float pd = acc[i][0] * dv.x + acc[i][1] * dv.y + acc[i][2] * dv.z + acc[i][3] * dv.w;
            ps += __shfl_xor_sync(0xffffffffu, ps, 1);
            pd += __shfl_xor_sync(0xffffffffu, pd, 1);
            ps += __shfl_xor_sync(0xffffffffu, ps, 2);
            pd += __shfl_xor_sync(0xffffffffu, pd, 2);
            int row = m0 + ty * 4 + i;
            if (H == 4) {
                if ((tx & 3) == 0 && row < NN) {
                    g_asrc[row * 4 + (tx >> 2)] = ps;
                    g_adst[row * 4 + (tx >> 2)] = pd;
                }
            } else {
                ps += __shfl_xor_sync(0xffffffffu, ps, 4);
                pd += __shfl_xor_sync(0xffffffffu, pd, 4);
                ps += __shfl_xor_sync(0xffffffffu, ps, 8);
                pd += __shfl_xor_sync(0xffffffffu, pd, 8);
                if (tx == 0 && row < NN) {
                    g_asrc[row] = ps;
                    g_adst[row] = pd;
                }
            }
        }
    }
}

// ---------------- per-edge weight precompute (lane-parallel: 4 exps/edge) ---
__device__ void wgt4_phase() {
    for (int e = blockIdx.x * NTHR + threadIdx.x; e < EE; e += GRID * NTHR) {
        int s = g_srcs[e];
        int d = g_dsts[e];
        float4 av = *reinterpret_cast<const float4*>(&g_asrc[s * 4]);
        float4 dv = *reinterpret_cast<const float4*>(&g_adst[d * 4]);
        float4 w;
        w.x = __expf(lrelu(av.x + dv.x));
        w.y = __expf(lrelu(av.y + dv.y));
        w.z = __expf(lrelu(av.z + dv.z));
        w.w = __expf(lrelu(av.w + dv.w));
        *reinterpret_cast<float4*>(&g_w[(size_t)e * 4]) = w;
    }
}

__device__ void wgt1_phase() {
    for (int e = blockIdx.x * NTHR + threadIdx.x; e < EE; e += GRID * NTHR) {
        g_w[e] = __expf(lrelu(g_asrc[g_srcs[e]] + g_adst[g_dsts[e]]));
    }
}

// ---------------- edge aggregation: contiguous per-warp segments ------------
// 344 consecutive edges per warp; accumulators carried across 8-edge chunks,
// flushed (REDG) only at dst-run boundaries (~12 flushes/warp vs ~43 before).
__device__ void eagg4_phase(const float* __restrict__ h) {
    const int lane = threadIdx.x & 31;
    const int w = (blockIdx.x * NTHR + threadIdx.x) >> 5;
    const int e0 = w * EPW;
    if (e0 >= EE) return;
    const int e1 = min(e0 + EPW, EE);
    const int c0 = lane, c1 = lane + 32;
    const bool hi = lane >= 16;
    const int h0 = hi ? 1 : 0;
    const int h1 = 2 + h0;

    float acc0 = 0.f, acc1 = 0.f, ss0 = 0.f, ss1 = 0.f;
    int dcur = g_dsts[e0];

    for (int base = e0; base < e1; base += 8) {   // e0,e1 multiples of 8
        int s[8], d[8];
#pragma unroll
        for (int j = 0; j < 8; j++) s[j] = g_srcs[base + j];
#pragma unroll
        for (int j = 0; j < 8; j++) d[j] = g_dsts[base + j];
#pragma unroll
        for (int half = 0; half < 2; half++) {
            const int o = half * 4;
            float w0[4], w1[4], hv0[4], hv1[4];
#pragma unroll
            for (int j = 0; j < 4; j++) {
                float4 wv = *reinterpret_cast<const float4*>(&g_w[(size_t)(base + o + j) * 4]);
                w0[j] = hi ? wv.y : wv.x;
                w1[j] = hi ? wv.w : wv.z;
            }
#pragma unroll
            for (int j = 0; j < 4; j++) {
                hv0[j] = h[(size_t)s[o + j] * 64 + c0];
                hv1[j] = h[(size_t)s[o + j] * 64 + c1];
            }
#pragma unroll
            for (int j = 0; j < 4; j++) {
                if (d[o + j] != dcur) {          // uniform branch
                    atomicAdd(&g_acc[(size_t)dcur * 64 + c0], acc0);
                    atomicAdd(&g_acc[(size_t)dcur * 64 + c1], acc1);
                    if ((lane & 15) == 0) {
                        atomicAdd(&g_sum[dcur * 4 + h0], ss0);
                        atomicAdd(&g_sum[dcur * 4 + h1], ss1);
                    }
                    acc0 = acc1 = ss0 = ss1 = 0.f;
                    dcur = d[o + j];
                }
                acc0 += w0[j] * hv0[j];
                acc1 += w1[j] * hv1[j];
                ss0 += w0[j];
                ss1 += w1[j];
            }
        }
    }
    atomicAdd(&g_acc[(size_t)dcur * 64 + c0], acc0);
    atomicAdd(&g_acc[(size_t)dcur * 64 + c1], acc1);
    if ((lane & 15) == 0) {
        atomicAdd(&g_sum[dcur * 4 + h0], ss0);
        atomicAdd(&g_sum[dcur * 4 + h1], ss1);
    }
}

__device__ void eagg1_phase(const float* __restrict__ h) {
    const int lane = threadIdx.x & 31;
    const int w = (blockIdx.x * NTHR + threadIdx.x) >> 5;
    const int e0 = w * EPW;
    if (e0 >= EE) return;
    const int e1 = min(e0 + EPW, EE);
    const int c0 = lane, c1 = lane + 32;
    const bool use1 = lane < 8;

    float acc0 = 0.f, acc1 = 0.f, ss = 0.f;
    int dcur = g_dsts[e0];

    for (int base = e0; base < e1; base += 8) {
        int s[8], d[8];
#pragma unroll
        for (int j = 0; j < 8; j++) s[j] = g_srcs[base + j];
#pragma unroll
        for (int j = 0; j < 8; j++) d[j] = g_dsts[base + j];
#pragma unroll
        for (int half = 0; half < 2; half++) {
            const int o = half * 4;
            float wv[4], hv0[4], hv1[4];
#pragma unroll
            for (int j = 0; j < 4; j++) wv[j] = g_w[base + o + j];
#pragma unroll
            for (int j = 0; j < 4; j++) {
                hv0[j] = h[(size_t)s[o + j] * 40 + c0];
                hv1[j] = use1 ? h[(size_t)s[o + j] * 40 + c1] : 0.f;
            }
#pragma unroll
            for (int j = 0; j < 4; j++) {
                if (d[o + j] != dcur) {
                    atomicAdd(&g_acc[(size_t)dcur * 64 + c0], acc0);
                    if (use1) atomicAdd(&g_acc[(size_t)dcur * 64 + c1], acc1);
                    if (lane == 0) atomicAdd(&g_sum[dcur * 4], ss);
                    acc0 = acc1 = ss = 0.f;
                    dcur = d[o + j];
                }
                acc0 += wv[j] * hv0[j];
                acc1 += wv[j] * hv1[j];
                ss += wv[j];
            }
        }
    }
    atomicAdd(&g_acc[(size_t)dcur * 64 + c0], acc0);
    if (use1) atomicAdd(&g_acc[(size_t)dcur * 64 + c1], acc1);
    if (lane == 0) atomicAdd(&g_sum[dcur * 4], ss);
}

// ---------------- post phases ------------------------------------------------
__device__ void post4_phase(float* sm, const float* __restrict__ h,
                            const float* __restrict__ bias, float* __restrict__ out) {
    const int c = threadIdx.x & 63;
    const int head = c >> 4;
    const float bs = bias[c];
    float s_acc = 0.f, q_acc = 0.f;
    for (int idx = blockIdx.x * NTHR + threadIdx.x; idx < NN * 64; idx += GRID * NTHR) {
        int v = idx >> 6;
        float ws = __expf(lrelu(g_asrc[v * 4 + head] + g_adst[v * 4 + head]));
        float o = (g_acc[idx] + ws * h[idx]) / (g_sum[v * 4 + head] + ws + 1e-16f) + bs;
        out[idx] = o;
        g_acc[idx] = 0.f;
        s_acc += o;
        q_acc += o * o;
    }
    float* shs = sm;
    float* shq = sm + 256;
    shs[threadIdx.x] = s_acc;
    shq[threadIdx.x] = q_acc;
    __syncthreads();
    if (threadIdx.x < 64) {
        float s = shs[threadIdx.x] + shs[threadIdx.x + 64] + shs[threadIdx.x + 128] + shs[threadIdx.x + 192];
        float q = shq[threadIdx.x] + shq[threadIdx.x + 64] + shq[threadIdx.x + 128] + shq[threadIdx.x + 192];
        atomicAdd(&g_stat[threadIdx.x], s);
        atomicAdd(&g_stat[64 + threadIdx.x], q);
    }
    __syncthreads();
}

__device__ void bnfinal_phase(const float* __restrict__ g, const float* __restrict__ beta) {
    if (blockIdx.x == 0 && threadIdx.x < 64) {
        int c = threadIdx.x;
        float mean = g_stat[c] * (1.0f / NN);
        float var = g_stat[64 + c] * (1.0f / NN) - mean * mean;
        float sc = g[c] * rsqrtf(var + 1e-5f);
        g_stat[128 + c] = sc;
        g_stat[192 + c] = beta[c] - mean * sc;
        g_stat[c] = 0.f;
        g_stat[64 + c] = 0.f;
    }
    float4 z = make_float4(0.f, 0.f, 0.f, 0.f);
    float4* s4 = reinterpret_cast<float4*>(g_sum);
    for (int i = blockIdx.x * NTHR + threadIdx.x; i < NN; i += GRID * NTHR)
        s4[i] = z;
}

__device__ void post1_phase(const float* __restrict__ h, const float* __restrict__ bias,
                            float* __restrict__ out) {
    const int lane = threadIdx.x & 31;
    const int warp0 = (blockIdx.x * NTHR + threadIdx.x) >> 5;
    const int c0 = lane, c1 = lane + 32;
    const bool use1 = lane < 8;
    for (int gw = warp0; gw < NN; gw += NWARP) {
        float ws = __expf(lrelu(g_asrc[gw] + g_adst[gw]));
        float inv = 1.f / (g_sum[gw * 4] + ws + 1e-16f);
        float a0 = g_acc[(size_t)gw * 64 + c0];
        float a1 = use1 ? g_acc[(size_t)gw * 64 + c1] : 0.f;
        float o0 = (a0 + ws * h[(size_t)gw * 40 + c0]) * inv + bias[c0];
        float o1 = use1 ? ((a1 + ws * h[(size_t)gw * 40 + c1]) * inv + bias[c1]) : neg_inf();
        float m = fmaxf(o0, o1);
#pragma unroll
        for (int off = 16; off; off >>= 1) m = fmaxf(m, __shfl_xor_sync(0xffffffffu, m, off));
        float se = __expf(o0 - m) + (use1 ? __expf(o1 - m) : 0.f);
#pragma unroll
        for (int off = 16; off; off >>= 1) se += __shfl_xor_sync(0xffffffffu, se, off);
        float ls = __logf(se);
        out[(size_t)gw * 40 + c0] = o0 - m - ls;
        if (use1) out[(size_t)gw * 40 + c1] = o1 - m - ls;
    }
}

// ---------------- THE mega-kernel --------------------------------------------
__global__ __launch_bounds__(NTHR, 4) void k_mega(
    const float* __restrict__ x, const int* __restrict__ ei,
    const float* __restrict__ W0, const float* __restrict__ as0, const float* __restrict__ ad0,
    const float* __restrict__ b0, const float* __restrict__ g0, const float* __restrict__ be0,
    const float* __restrict__ W1, const float* __restrict__ as1, const float* __restrict__ ad1,
    const float* __restrict__ b1, const float* __restrict__ g1, const float* __restrict__ be1,
    const float* __restrict__ W2, const float* __restrict__ as2, const float* __restrict__ ad2,
    const float* __restrict__ b2, float* __restrict__ out) {
    __shared__ float smbuf[4480];
    const int tid = threadIdx.x;
    const int gt = blockIdx.x * NTHR + tid;

    // P0: zero all scratch (vectorized)
    {
        float4 z = make_float4(0.f, 0.f, 0.f, 0.f);
        float4* a4 = reinterpret_cast<float4*>(g_acc);
        for (int i = gt; i < NN * 16; i += GRID * NTHR) a4[i] = z;
        float4* s4 = reinterpret_cast<float4*>(g_sum);
        for (int i = gt; i < NN; i += GRID * NTHR) s4[i] = z;
        for (int i = gt; i < NN; i += GRID * NTHR) g_cursor[i] = 0;
        if (gt < 128) g_stat[gt] = 0.f;
    }
    gridsync();

    // P1: count in-degrees
    for (int e = gt; e < EE; e += GRID * NTHR)
        atomicAdd(&g_cursor[ei[EE + e]], 1);
    gridsync();

    // P2: per-block local exclusive scan of counts
    const int CH = (NN + GRID - 1) / GRID;   // 85
    const int start = blockIdx.x * CH;
    int* si = (int*)smbuf;
    for (int i = tid; i < CH; i += NTHR)
        si[i] = (start + i < NN) ? g_cursor[start + i] : 0;
    __syncthreads();
    if (tid == 0) {
        int run = 0;
        for (int i = 0; i < CH; i++) { int v = si[i]; si[i] = run; run += v; }
        si[CH] = run;
        g_part[blockIdx.x] = run;
    }
    __syncthreads();
    gridsync();

    // P3: block 0 scans block totals
    if (blockIdx.x == 0) {
        int* sp = (int*)(smbuf + 2304);
        for (int i = tid; i < GRID; i += NTHR) sp[i] = g_part[i];
        __syncthreads();
        if (tid == 0) {
            int run = 0;
            for (int i = 0; i < GRID; i++) { int v = sp[i]; sp[i] = run; run += v; }
        }
        __syncthreads();
        for (int i = tid; i < GRID; i += NTHR) g_partpre[i] = sp[i];
    }
    gridsync();

    // P4: write rowptr + scatter cursors
    {
        const int base = g_partpre[blockIdx.x];
        for (int i = tid; i < CH; i += NTHR) {
            int v = start + i;
            if (v < NN) {
                int rp = base + si[i];
                g_rowptr[v] = rp;
                g_cursor[v] = rp;
            }
        }
        if (blockIdx.x == 0 && tid == 0) g_rowptr[NN] = EE;
    }
    gridsync();

    // P5: scatter edges into CSR (dst-sorted)
    for (int e = gt; e < EE; e += GRID * NTHR) {
        int s = ei[e];
        int d = ei[EE + e];
        int pos = atomicAdd(&g_cursor[d], 1);
        g_srcs[pos] = s;
        g_dsts[pos] = d;
    }
    gridsync();

    // ---- layer 0 ----
    gemm_phase<128, 64, false, 4>(smbuf, x, W0, g_h, as0, ad0);
    gridsync();
    wgt4_phase();
    gridsync();
    eagg4_phase(g_h);
    gridsync();
    post4_phase(smbuf, g_h, b0, g_agg);
    gridsync();
    bnfinal_phase(g0, be0);
    gridsync();

    // ---- layer 1 ----
    gemm_phase<64, 64, true, 4>(smbuf, g_agg, W1, g_h, as1, ad1);
    gridsync();
    wgt4_phase();
    gridsync();
    eagg4_phase(g_h);
    gridsync();
    post4_phase(smbuf, g_h, b1, g_agg);
    gridsync();
    bnfinal_phase(g1, be1);
    gridsync();

    // ---- layer 2 ----
    gemm_phase<64, 40, true, 1>(smbuf, g_agg, W2, g_h, as2, ad2);
    gridsync();
    wgt1_phase();
    gridsync();
    eagg1_phase(g_h);
    gridsync();
    post1_phase(g_h, b2, out);
}

// ---------------- launch ------------------------------------------------------
extern "C" void kernel_launch(void* const* d_in, const int* in_sizes, int n_in,
                              void* d_out, int out_size) {
    const float* x   = (const float*)d_in[0];
    const int*   ei  = (const int*)d_in[1];
    const float* W0  = (const float*)d_in[2];
    const float* as0 = (const float*)d_in[3];
    const float* ad0 = (const float*)d_in[4];
    const float* b0  = (const float*)d_in[5];
    const float* g0  = (const float*)d_in[6];
    const float* be0 = (const float*)d_in[7];
    const float* W1  = (const float*)d_in[8];
    const float* as1 = (const float*)d_in[9];
    const float* ad1 = (const float*)d_in[10];
    const float* b1  = (const float*)d_in[11];
    const float* b1_ = b1;
    const float* g1  = (const float*)d_in[12];
    const float* be1 = (const float*)d_in[13];
    const float* W2  = (const float*)d_in[14];
    const float* as2 = (const float*)d_in[15];
    const float* ad2 = (const float*)d_in[16];
    const float* b2  = (const float*)d_in[17];
    float* out = (float*)d_out;
    (void)b1_;

    k_mega<<<GRID, NTHR>>>(x, ei, W0, as0, ad0, b0, g0, be0,
                           W1, as1, ad1, b1, g1, be1,
                           W2, as2, ad2, b2, out);
}

// round 11
// speedup vs baseline: 21.1657x; 1.0854x over previous
#include <cuda_runtime.h>

#define NN 50000
#define EE 1600000
#define GRID 608          // 4 blocks/SM × 152 SMs (GB300)
#define NTHR 256
#define NWARP (GRID * NTHR / 32)   // 4864
#define EPW 336                    // edges per warp (mult of 8; 336*4864 ≥ EE)

// ---------------- scratch (device globals) ----------------------------------
__device__ float g_h[NN * 64];
__device__ float g_agg[NN * 64];
__device__ float g_acc[NN * 64];
__device__ float g_w[(size_t)EE * 4];   // per-edge weights, layout [h0,h2,h1,h3]
__device__ float g_asrc[NN * 4];
__device__ float g_adst[NN * 4];
__device__ float g_sum[NN * 4];
__device__ int   g_rowptr[NN + 1];
__device__ int   g_cursor[NN];
__device__ int2  g_edge[EE];      // packed (src,dst), dst-sorted
__device__ float g_stat[128];     // raw BN sums/sumsq
__device__ int   g_part[GRID];
__device__ int   g_partpre[GRID];
__device__ volatile int g_bar_count;
__device__ volatile int g_bar_gen;

__device__ __forceinline__ float neg_inf() { return __int_as_float(0xff800000); }
__device__ __forceinline__ float lrelu(float e) { return fmaxf(e, 0.2f * e); }

// ---------------- grid-wide barrier (all blocks co-resident) ----------------
__device__ __forceinline__ void gridsync() {
    __syncthreads();
    if (threadIdx.x == 0) {
        __threadfence();
        int gen = g_bar_gen;
        if (atomicAdd((int*)&g_bar_count, 1) == GRID - 1) {
            g_bar_count = 0;
            __threadfence();
            g_bar_gen = gen + 1;
        } else {
            while (g_bar_gen == gen) { __nanosleep(32); }
        }
        __threadfence();
    }
    __syncthreads();
}

// ---------------- GEMM phase + fused BN-prep + alpha epilogue ---------------
// BN: derive scale/shift from raw g_stat sums (redundantly per block, cheap).
// Also zeroes g_sum for the upcoming aggregation phase.
template <int K, int NO, bool BN, int H>
__device__ void gemm_phase(float* sm, float* bnsc, float* bnsh,
                           const float* __restrict__ A,
                           const float* __restrict__ W, float* __restrict__ C,
                           const float* __restrict__ a_s, const float* __restrict__ a_d,
                           const float* __restrict__ bn_g, const float* __restrict__ bn_b) {
    float (*As)[36] = (float(*)[36])sm;          // 64*36 = 2304 floats
    float (*Ws)[64] = (float(*)[64])(sm + 2304); // 32*64 = 2048 floats
    const int tid = threadIdx.x;
    const int ty = tid >> 4;
    const int tx = tid & 15;
    const int lr = tid >> 3;
    const int lc = (tid & 7) * 4;
    const int ntile = (NN + 63) / 64;

    if (BN && tid < 64) {
        float mean = g_stat[tid] * (1.0f / NN);
        float var = g_stat[64 + tid] * (1.0f / NN) - mean * mean;
        float sc = bn_g[tid] * rsqrtf(var + 1e-5f);
        bnsc[tid] = sc;
        bnsh[tid] = bn_b[tid] - mean * sc;
    }
    // zero softmax denominators for this layer's aggregation
    {
        float4 z = make_float4(0.f, 0.f, 0.f, 0.f);
        float4* s4 = reinterpret_cast<float4*>(g_sum);
        for (int i = blockIdx.x * NTHR + tid; i < NN; i += GRID * NTHR) s4[i] = z;
    }
    __syncthreads();

    for (int tile = blockIdx.x; tile < ntile; tile += GRID) {
        const int m0 = tile * 64;
        float acc[4][4] = {};
        for (int kt = 0; kt < K; kt += 32) {
            float4 sc, sh;
            if (BN) {
                sc = *reinterpret_cast<const float4*>(&bnsc[kt + lc]);
                sh = *reinterpret_cast<const float4*>(&bnsh[kt + lc]);
            }
#pragma unroll
            for (int rr = 0; rr < 64; rr += 32) {
                int row = m0 + lr + rr;
                float4 v = make_float4(0.f, 0.f, 0.f, 0.f);
                if (row < NN)
                    v = *reinterpret_cast<const float4*>(A + (size_t)row * K + kt + lc);
                if (BN) {
                    v.x = fmaxf(v.x * sc.x + sh.x, 0.f);
                    v.y = fmaxf(v.y * sc.y + sh.y, 0.f);
                    v.z = fmaxf(v.z * sc.z + sh.z, 0.f);
                    v.w = fmaxf(v.w * sc.w + sh.w, 0.f);
                }
                *reinterpret_cast<float4*>(&As[lr + rr][lc]) = v;
            }
#pragma unroll
            for (int kk = 0; kk < 32; kk += 16) {
                int k = ty + kk;
                int c = tx * 4;
                float4 v = make_float4(0.f, 0.f, 0.f, 0.f);
                if (NO == 64 || c < NO)
                    v = *reinterpret_cast<const float4*>(W + (size_t)(kt + k) * NO + c);
                *reinterpret_cast<float4*>(&Ws[k][c]) = v;
            }
            __syncthreads();
#pragma unroll
            for (int k = 0; k < 32; k++) {
                float a0 = As[ty * 4 + 0][k];
                float a1 = As[ty * 4 + 1][k];
                float a2 = As[ty * 4 + 2][k];
                float a3 = As[ty * 4 + 3][k];
                float4 b = *reinterpret_cast<const float4*>(&Ws[k][tx * 4]);
                acc[0][0] += a0 * b.x; acc[0][1] += a0 * b.y; acc[0][2] += a0 * b.z; acc[0][3] += a0 * b.w;
                acc[1][0] += a1 * b.x; acc[1][1] += a1 * b.y; acc[1][2] += a1 * b.z; acc[1][3] += a1 * b.w;
                acc[2][0] += a2 * b.x; acc[2][1] += a2 * b.y; acc[2][2] += a2 * b.z; acc[2][3] += a2 * b.w;
                acc[3][0] += a3 * b.x; acc[3][1] += a3 * b.y; acc[3][2] += a3 * b.z; acc[3][3] += a3 * b.w;
            }
            __syncthreads();
        }
#pragma unroll
        for (int i = 0; i < 4; i++) {
            int row = m0 + ty * 4 + i;
            if (row < NN && (NO == 64 || tx * 4 < NO)) {
                float4 v = make_float4(acc[i][0], acc[i][1], acc[i][2], acc[i][3]);
                *reinterpret_cast<float4*>(C + (size_t)row * NO + tx * 4) = v;
            }
        }
        const bool colok = (NO == 64) || (tx * 4 < NO);
        float4 av = make_float4(0.f, 0.f, 0.f, 0.f), dv = av;
        if (colok) {
            av = *reinterpret_cast<const float4*>(a_s + tx * 4);
            dv = *reinterpret_cast<const float4*>(a_d + tx * 4);
        }
#pragma unroll
        for (int i = 0; i < 4; i++) {
            float ps = acc[i][0] * av.x + acc[i][1] * av.y + acc[i][2] * av.z + acc[i][3] * av.w;
            float pd = acc[i][0] * dv.x + acc[i][1] * dv.y + acc[i][2] * dv.z + acc[i][3] * dv.w;
            ps += __shfl_xor_sync(0xffffffffu, ps, 1);
            pd += __shfl_xor_sync(0xffffffffu, pd, 1);
            ps += __shfl_xor_sync(0xffffffffu, ps, 2);
            pd += __shfl_xor_sync(0xffffffffu, pd, 2);
            int row = m0 + ty * 4 + i;
            if (H == 4) {
                if ((tx & 3) == 0 && row < NN) {
                    g_asrc[row * 4 + (tx >> 2)] = ps;
                    g_adst[row * 4 + (tx >> 2)] = pd;
                }
            } else {
                ps += __shfl_xor_sync(0xffffffffu, ps, 4);
                pd += __shfl_xor_sync(0xffffffffu, pd, 4);
                ps += __shfl_xor_sync(0xffffffffu, ps, 8);
                pd += __shfl_xor_sync(0xffffffffu, pd, 8);
                if (tx == 0 && row < NN) {
                    g_asrc[row] = ps;
                    g_adst[row] = pd;
                }
            }
        }
    }
}

// ---------------- per-edge weight precompute (lane-parallel) ----------------
// Writes head-paired layout [h0, h2, h1, h3]: lane group hi loads float2 at
// offset 2*hi and gets (head hi, head 2+hi). Also re-zeroes g_stat for the
// next BN-stat accumulation (raw sums already consumed by this layer's GEMM).
__device__ void wgt4_phase() {
    const int gt = blockIdx.x * NTHR + threadIdx.x;
    if (gt < 128) g_stat[gt] = 0.f;
    for (int e = gt; e < EE; e += GRID * NTHR) {
        int2 ed = g_edge[e];
        float4 av = *reinterpret_cast<const float4*>(&g_asrc[ed.x * 4]);
        float4 dv = *reinterpret_cast<const float4*>(&g_adst[ed.y * 4]);
        float4 w;
        w.x = __expf(lrelu(av.x + dv.x));   // head 0
        w.y = __expf(lrelu(av.z + dv.z));   // head 2
        w.z = __expf(lrelu(av.y + dv.y));   // head 1
        w.w = __expf(lrelu(av.w + dv.w));   // head 3
        *reinterpret_cast<float4*>(&g_w[(size_t)e * 4]) = w;
    }
}

__device__ void wgt1_phase() {
    for (int e = blockIdx.x * NTHR + threadIdx.x; e < EE; e += GRID * NTHR) {
        int2 ed = g_edge[e];
        g_w[e] = __expf(lrelu(g_asrc[ed.x] + g_adst[ed.y]));
    }
}

// ---------------- edge aggregation: contiguous per-warp segments ------------
__device__ void eagg4_phase(const float* __restrict__ h) {
    const int lane = threadIdx.x & 31;
    const int w = (blockIdx.x * NTHR + threadIdx.x) >> 5;
    const int e0 = w * EPW;
    if (e0 >= EE) return;
    const int e1 = min(e0 + EPW, EE);
    const int c0 = lane, c1 = lane + 32;
    const bool hi = lane >= 16;
    const int h0 = hi ? 1 : 0;
    const int h1 = 2 + h0;
    const int woff = 2 * (hi ? 1 : 0);

    float acc0 = 0.f, acc1 = 0.f, ss0 = 0.f, ss1 = 0.f;
    int dcur = g_edge[e0].y;

    for (int base = e0; base < e1; base += 8) {   // e0,e1 multiples of 8
        int2 ed[8];
#pragma unroll
        for (int j = 0; j < 8; j++) ed[j] = g_edge[base + j];   // broadcast
#pragma unroll
        for (int half = 0; half < 2; half++) {
            const int o = half * 4;
            float w0[4], w1[4], hv0[4], hv1[4];
#pragma unroll
            for (int j = 0; j < 4; j++) {
                float2 wv = *reinterpret_cast<const float2*>(
                    &g_w[(size_t)(base + o + j) * 4 + woff]);
                w0[j] = wv.x;
                w1[j] = wv.y;
            }
#pragma unroll
            for (int j = 0; j < 4; j++) {
                hv0[j] = h[(size_t)ed[o + j].x * 64 + c0];
                hv1[j] = h[(size_t)ed[o + j].x * 64 + c1];
            }
#pragma unroll
            for (int j = 0; j < 4; j++) {
                if (ed[o + j].y != dcur) {       // uniform branch
                    atomicAdd(&g_acc[(size_t)dcur * 64 + c0], acc0);
                    atomicAdd(&g_acc[(size_t)dcur * 64 + c1], acc1);
                    if ((lane & 15) == 0) {
                        atomicAdd(&g_sum[dcur * 4 + h0], ss0);
                        atomicAdd(&g_sum[dcur * 4 + h1], ss1);
                    }
                    acc0 = acc1 = ss0 = ss1 = 0.f;
                    dcur = ed[o + j].y;
                }
                acc0 += w0[j] * hv0[j];
                acc1 += w1[j] * hv1[j];
                ss0 += w0[j];
                ss1 += w1[j];
            }
        }
    }
    atomicAdd(&g_acc[(size_t)dcur * 64 + c0], acc0);
    atomicAdd(&g_acc[(size_t)dcur * 64 + c1], acc1);
    if ((lane & 15) == 0) {
        atomicAdd(&g_sum[dcur * 4 + h0], ss0);
        atomicAdd(&g_sum[dcur * 4 + h1], ss1);
    }
}

__device__ void eagg1_phase(const float* __restrict__ h) {
    const int lane = threadIdx.x & 31;
    const int w = (blockIdx.x * NTHR + threadIdx.x) >> 5;
    const int e0 = w * EPW;
    if (e0 >= EE) return;
    const int e1 = min(e0 + EPW, EE);
    const int c0 = lane, c1 = lane + 32;
    const bool use1 = lane < 8;

    float acc0 = 0.f, acc1 = 0.f, ss = 0.f;
    int dcur = g_edge[e0].y;

    for (int base = e0; base < e1; base += 8) {
        int2 ed[8];
#pragma unroll
        for (int j = 0; j < 8; j++) ed[j] = g_edge[base + j];
#pragma unroll
        for (int half = 0; half < 2; half++) {
            const int o = half * 4;
            float wv[4], hv0[4], hv1[4];
#pragma unroll
            for (int j = 0; j < 4; j++) wv[j] = g_w[base + o + j];
#pragma unroll
            for (int j = 0; j < 4; j++) {
                hv0[j] = h[(size_t)ed[o + j].x * 40 + c0];
                hv1[j] = use1 ? h[(size_t)ed[o + j].x * 40 + c1] : 0.f;
            }
#pragma unroll
            for (int j = 0; j < 4; j++) {
                if (ed[o + j].y != dcur) {
                    atomicAdd(&g_acc[(size_t)dcur * 64 + c0], acc0);
                    if (use1) atomicAdd(&g_acc[(size_t)dcur * 64 + c1], acc1);
                    if (lane == 0) atomicAdd(&g_sum[dcur * 4], ss);
                    acc0 = acc1 = ss = 0.f;
                    dcur = ed[o + j].y;
                }
                acc0 += wv[j] * hv0[j];
                acc1 += wv[j] * hv1[j];
                ss += wv[j];
            }
        }
    }
    atomicAdd(&g_acc[(size_t)dcur * 64 + c0], acc0);
    if (use1) atomicAdd(&g_acc[(size_t)dcur * 64 + c1], acc1);
    if (lane == 0) atomicAdd(&g_sum[dcur * 4], ss);
}

// ---------------- post phases ------------------------------------------------
__device__ void post4_phase(float* sm, const float* __restrict__ h,
                            const float* __restrict__ bias, float* __restrict__ out) {
    const int c = threadIdx.x & 63;    // constant per thread (stride % 64 == 0)
    const int head = c >> 4;
    const float bs = bias[c];
    float s_acc = 0.f, q_acc = 0.f;
    for (int idx = blockIdx.x * NTHR + threadIdx.x; idx < NN * 64; idx += GRID * NTHR) {
        int v = idx >> 6;
        float ws = __expf(lrelu(g_asrc[v * 4 + head] + g_adst[v * 4 + head]));
        float o = (g_acc[idx] + ws * h[idx]) / (g_sum[v * 4 + head] + ws + 1e-16f) + bs;
        out[idx] = o;
        g_acc[idx] = 0.f;
        s_acc += o;
        q_acc += o * o;
    }
    float* shs = sm;
    float* shq = sm + 256;
    shs[threadIdx.x] = s_acc;
    shq[threadIdx.x] = q_acc;
    __syncthreads();
    if (threadIdx.x < 64) {
        float s = shs[threadIdx.x] + shs[threadIdx.x + 64] + shs[threadIdx.x + 128] + shs[threadIdx.x + 192];
        float q = shq[threadIdx.x] + shq[threadIdx.x + 64] + shq[threadIdx.x + 128] + shq[threadIdx.x + 192];
        atomicAdd(&g_stat[threadIdx.x], s);
        atomicAdd(&g_stat[64 + threadIdx.x], q);
    }
    __syncthreads();
}

__device__ void post1_phase(const float* __restrict__ h, const float* __restrict__ bias,
                            float* __restrict__ out) {
    const int lane = threadIdx.x & 31;
    const int warp0 = (blockIdx.x * NTHR + threadIdx.x) >> 5;
    const int c0 = lane, c1 = lane + 32;
    const bool use1 = lane < 8;
    for (int gw = warp0; gw < NN; gw += NWARP) {
        float ws = __expf(lrelu(g_asrc[gw] + g_adst[gw]));
        float inv = 1.f / (g_sum[gw * 4] + ws + 1e-16f);
        float a0 = g_acc[(size_t)gw * 64 + c0];
        float a1 = use1 ? g_acc[(size_t)gw * 64 + c1] : 0.f;
        float o0 = (a0 + ws * h[(size_t)gw * 40 + c0]) * inv + bias[c0];
        float o1 = use1 ? ((a1 + ws * h[(size_t)gw * 40 + c1]) * inv + bias[c1]) : neg_inf();
        float m = fmaxf(o0, o1);
#pragma unroll
        for (int off = 16; off; off >>= 1) m = fmaxf(m, __shfl_xor_sync(0xffffffffu, m, off));
        float se = __expf(o0 - m) + (use1 ? __expf(o1 - m) : 0.f);
#pragma unroll
        for (int off = 16; off; off >>= 1) se += __shfl_xor_sync(0xffffffffu, se, off);
        float ls = __logf(se);
        out[(size_t)gw * 40 + c0] = o0 - m - ls;
        if (use1) out[(size_t)gw * 40 + c1] = o1 - m - ls;
    }
}

// ---------------- THE mega-kernel --------------------------------------------
__global__ __launch_bounds__(NTHR, 4) void k_mega(
    const float* __restrict__ x, const int* __restrict__ ei,
    const float* __restrict__ W0, const float* __restrict__ as0, const float* __restrict__ ad0,
    const float* __restrict__ b0, const float* __restrict__ g0, const float* __restrict__ be0,
    const float* __restrict__ W1, const float* __restrict__ as1, const float* __restrict__ ad1,
    const float* __restrict__ b1, const float* __restrict__ g1, const float* __restrict__ be1,
    const float* __restrict__ W2, const float* __restrict__ as2, const float* __restrict__ ad2,
    const float* __restrict__ b2, float* __restrict__ out) {
    __shared__ float smbuf[4480];
    __shared__ float bnsc[64], bnsh[64];
    const int tid = threadIdx.x;
    const int gt = blockIdx.x * NTHR + tid;

    // P0: zero scratch (g_sum zeroed per-layer inside gemm_phase)
    {
        float4 z = make_float4(0.f, 0.f, 0.f, 0.f);
        float4* a4 = reinterpret_cast<float4*>(g_acc);
        for (int i = gt; i < NN * 16; i += GRID * NTHR) a4[i] = z;
        for (int i = gt; i < NN; i += GRID * NTHR) g_cursor[i] = 0;
        if (gt < 128) g_stat[gt] = 0.f;
    }
    gridsync();

    // P1: count in-degrees
    for (int e = gt; e < EE; e += GRID * NTHR)
        atomicAdd(&g_cursor[ei[EE + e]], 1);
    gridsync();

    // P2: per-block local exclusive scan of counts
    const int CH = (NN + GRID - 1) / GRID;   // 83
    const int start = blockIdx.x * CH;
    int* si = (int*)smbuf;
    for (int i = tid; i < CH; i += NTHR)
        si[i] = (start + i < NN) ? g_cursor[start + i] : 0;
    __syncthreads();
    if (tid == 0) {
        int run = 0;
        for (int i = 0; i < CH; i++) { int v = si[i]; si[i] = run; run += v; }
        si[CH] = run;
        g_part[blockIdx.x] = run;
    }
    __syncthreads();
    gridsync();

    // P3: block 0 scans block totals
    if (blockIdx.x == 0) {
        int* sp = (int*)(smbuf + 2304);
        for (int i = tid; i < GRID; i += NTHR) sp[i] = g_part[i];
        __syncthreads();
        if (tid == 0) {
            int run = 0;
            for (int i = 0; i < GRID; i++) { int v = sp[i]; sp[i] = run; run += v; }
        }
        __syncthreads();
        for (int i = tid; i < GRID; i += NTHR) g_partpre[i] = sp[i];
    }
    gridsync();

    // P4: write rowptr + scatter cursors
    {
        const int base = g_partpre[blockIdx.x];
        for (int i = tid; i < CH; i += NTHR) {
            int v = start + i;
            if (v < NN) {
                int rp = base + si[i];
                g_rowptr[v] = rp;
                g_cursor[v] = rp;
            }
        }
        if (blockIdx.x == 0 && tid == 0) g_rowptr[NN] = EE;
    }
    gridsync();

    // P5: scatter edges into CSR (dst-sorted, packed int2)
    for (int e = gt; e < EE; e += GRID * NTHR) {
        int s = ei[e];
        int d = ei[EE + e];
        int pos = atomicAdd(&g_cursor[d], 1);
        g_edge[pos] = make_int2(s, d);
    }
    gridsync();

    // ---- layer 0 ----
    gemm_phase<128, 64, false, 4>(smbuf, bnsc, bnsh, x, W0, g_h, as0, ad0, g0, be0);
    gridsync();
    wgt4_phase();
    gridsync();
    eagg4_phase(g_h);
    gridsync();
    post4_phase(smbuf, g_h, b0, g_agg);
    gridsync();

    // ---- layer 1 ----
    gemm_phase<64, 64, true, 4>(smbuf, bnsc, bnsh, g_agg, W1, g_h, as1, ad1, g0, be0);
    gridsync();
    wgt4_phase();
    gridsync();
    eagg4_phase(g_h);
    gridsync();
    post4_phase(smbuf, g_h, b1, g_agg);
    gridsync();

    // ---- layer 2 ----
    gemm_phase<64, 40, true, 1>(smbuf, bnsc, bnsh, g_agg, W2, g_h, as2, ad2, g1, be1);
    gridsync();
    wgt1_phase();
    gridsync();
    eagg1_phase(g_h);
    gridsync();
    post1_phase(g_h, b2, out);
}

// ---------------- launch ------------------------------------------------------
extern "C" void kernel_launch(void* const* d_in, const int* in_sizes, int n_in,
                              void* d_out, int out_size) {
    const float* x   = (const float*)d_in[0];
    const int*   ei  = (const int*)d_in[1];
    const float* W0  = (const float*)d_in[2];
    const float* as0 = (const float*)d_in[3];
    const float* ad0 = (const float*)d_in[4];
    const float* b0  = (const float*)d_in[5];
    const float* g0  = (const float*)d_in[6];
    const float* be0 = (const float*)d_in[7];
    const float* W1  = (const float*)d_in[8];
    const float* as1 = (const float*)d_in[9];
    const float* ad1 = (const float*)d_in[10];
    const float* b1  = (const float*)d_in[11];
    const float* g1  = (const float*)d_in[12];
    const float* be1 = (const float*)d_in[13];
    const float* W2  = (const float*)d_in[14];
    const float* as2 = (const float*)d_in[15];
    const float* ad2 = (const float*)d_in[16];
    const float* b2  = (const float*)d_in[17];
    float* out = (float*)d_out;

    k_mega<<<GRID, NTHR>>>(x, ei, W0, as0, ad0, b0, g0, be0,
                           W1, as1, ad1, b1, g1, be1,
                           W2, as2, ad2, b2, out);
}

// round 12
// speedup vs baseline: 21.6473x; 1.0228x over previous
#include <cuda_runtime.h>

#define NN 50000
#define EE 1600000
#define GRID 608          // 4 blocks/SM × 152 SMs (GB300)
#define NTHR 256
#define NWARP (GRID * NTHR / 32)   // 4864
#define EPW 336                    // edges per warp (mult of 8; 336*4864 ≥ EE)

// ---------------- scratch (device globals) ----------------------------------
__device__ float g_h[NN * 64];
__device__ float g_agg[NN * 64];
__device__ float g_acc[NN * 64];
__device__ float g_w[(size_t)EE * 4];   // per-edge weights [h0,h1,h2,h3]
__device__ float g_asrc[NN * 4];
__device__ float g_adst[NN * 4];
__device__ float g_sum[NN * 4];
__device__ int   g_rowptr[NN + 1];
__device__ int   g_cursor[NN];
__device__ int2  g_edge[EE];      // packed (src,dst), dst-sorted
__device__ float g_stat[128];     // raw BN sums/sumsq
__device__ int   g_part[GRID];
__device__ int   g_partpre[GRID];
__device__ int   g_tilec[3];      // GEMM work-stealing counters (zeroed in P0)
__device__ volatile int g_bar_count;
__device__ volatile int g_bar_gen;

__device__ __forceinline__ float neg_inf() { return __int_as_float(0xff800000); }
__device__ __forceinline__ float lrelu(float e) { return fmaxf(e, 0.2f * e); }

// ---------------- grid-wide barrier (all blocks co-resident) ----------------
__device__ __forceinline__ void gridsync() {
    __syncthreads();
    if (threadIdx.x == 0) {
        __threadfence();
        int gen = g_bar_gen;
        if (atomicAdd((int*)&g_bar_count, 1) == GRID - 1) {
            g_bar_count = 0;
            __threadfence();
            g_bar_gen = gen + 1;
        } else {
            while (g_bar_gen == gen) { __nanosleep(32); }
        }
        __threadfence();
    }
    __syncthreads();
}

// ---------------- GEMM phase: work-stealing tiles + BN-prep + alpha epilogue -
template <int K, int NO, bool BN, int H>
__device__ void gemm_phase(float* sm, float* bnsc, float* bnsh, int* s_tile, int* ctr,
                           const float* __restrict__ A,
                           const float* __restrict__ W, float* __restrict__ C,
                           const float* __restrict__ a_s, const float* __restrict__ a_d,
                           const float* __restrict__ bn_g, const float* __restrict__ bn_b) {
    float (*As)[36] = (float(*)[36])sm;          // 64*36 = 2304 floats
    float (*Ws)[64] = (float(*)[64])(sm + 2304); // 32*64 = 2048 floats
    const int tid = threadIdx.x;
    const int ty = tid >> 4;
    const int tx = tid & 15;
    const int lr = tid >> 3;
    const int lc = (tid & 7) * 4;
    const int ntile = (NN + 63) / 64;

    if (BN && tid < 64) {
        float mean = g_stat[tid] * (1.0f / NN);
        float var = g_stat[64 + tid] * (1.0f / NN) - mean * mean;
        float sc = bn_g[tid] * rsqrtf(var + 1e-5f);
        bnsc[tid] = sc;
        bnsh[tid] = bn_b[tid] - mean * sc;
    }
    // zero softmax denominators for this layer's aggregation
    {
        float4 z = make_float4(0.f, 0.f, 0.f, 0.f);
        float4* s4 = reinterpret_cast<float4*>(g_sum);
        for (int i = blockIdx.x * NTHR + tid; i < NN; i += GRID * NTHR) s4[i] = z;
    }
    __syncthreads();

    for (;;) {
        if (tid == 0) *s_tile = atomicAdd(ctr, 1);
        __syncthreads();
        const int tile = *s_tile;
        if (tile >= ntile) break;
        const int m0 = tile * 64;
        float acc[4][4] = {};
        for (int kt = 0; kt < K; kt += 32) {
            float4 sc, sh;
            if (BN) {
                sc = *reinterpret_cast<const float4*>(&bnsc[kt + lc]);
                sh = *reinterpret_cast<const float4*>(&bnsh[kt + lc]);
            }
#pragma unroll
            for (int rr = 0; rr < 64; rr += 32) {
                int row = m0 + lr + rr;
                float4 v = make_float4(0.f, 0.f, 0.f, 0.f);
                if (row < NN)
                    v = *reinterpret_cast<const float4*>(A + (size_t)row * K + kt + lc);
                if (BN) {
                    v.x = fmaxf(v.x * sc.x + sh.x, 0.f);
                    v.y = fmaxf(v.y * sc.y + sh.y, 0.f);
                    v.z = fmaxf(v.z * sc.z + sh.z, 0.f);
                    v.w = fmaxf(v.w * sc.w + sh.w, 0.f);
                }
                *reinterpret_cast<float4*>(&As[lr + rr][lc]) = v;
            }
#pragma unroll
            for (int kk = 0; kk < 32; kk += 16) {
                int k = ty + kk;
                int c = tx * 4;
                float4 v = make_float4(0.f, 0.f, 0.f, 0.f);
                if (NO == 64 || c < NO)
                    v = *reinterpret_cast<const float4*>(W + (size_t)(kt + k) * NO + c);
                *reinterpret_cast<float4*>(&Ws[k][c]) = v;
            }
            __syncthreads();
#pragma unroll
            for (int k = 0; k < 32; k++) {
                float a0 = As[ty * 4 + 0][k];
                float a1 = As[ty * 4 + 1][k];
                float a2 = As[ty * 4 + 2][k];
                float a3 = As[ty * 4 + 3][k];
                float4 b = *reinterpret_cast<const float4*>(&Ws[k][tx * 4]);
                acc[0][0] += a0 * b.x; acc[0][1] += a0 * b.y; acc[0][2] += a0 * b.z; acc[0][3] += a0 * b.w;
                acc[1][0] += a1 * b.x; acc[1][1] += a1 * b.y; acc[1][2] += a1 * b.z; acc[1][3] += a1 * b.w;
                acc[2][0] += a2 * b.x; acc[2][1] += a2 * b.y; acc[2][2] += a2 * b.z; acc[2][3] += a2 * b.w;
                acc[3][0] += a3 * b.x; acc[3][1] += a3 * b.y; acc[3][2] += a3 * b.z; acc[3][3] += a3 * b.w;
            }
            __syncthreads();
        }
#pragma unroll
        for (int i = 0; i < 4; i++) {
            int row = m0 + ty * 4 + i;
            if (row < NN && (NO == 64 || tx * 4 < NO)) {
                float4 v = make_float4(acc[i][0], acc[i][1], acc[i][2], acc[i][3]);
                *reinterpret_cast<float4*>(C + (size_t)row * NO + tx * 4) = v;
            }
        }
        const bool colok = (NO == 64) || (tx * 4 < NO);
        float4 av = make_float4(0.f, 0.f, 0.f, 0.f), dv = av;
        if (colok) {
            av = *reinterpret_cast<const float4*>(a_s + tx * 4);
            dv = *reinterpret_cast<const float4*>(a_d + tx * 4);
        }
#pragma unroll
        for (int i = 0; i < 4; i++) {
            float ps = acc[i][0] * av.x + acc[i][1] * av.y + acc[i][2] * av.z + acc[i][3] * av.w;
            float pd = acc[i][0] * dv.x + acc[i][1] * dv.y + acc[i][2] * dv.z + acc[i][3] * dv.w;
            ps += __shfl_xor_sync(0xffffffffu, ps, 1);
            pd += __shfl_xor_sync(0xffffffffu, pd, 1);
            ps += __shfl_xor_sync(0xffffffffu, ps, 2);
            pd += __shfl_xor_sync(0xffffffffu, pd, 2);
            int row = m0 + ty * 4 + i;
            if (H == 4) {
                if ((tx & 3) == 0 && row < NN) {
                    g_asrc[row * 4 + (tx >> 2)] = ps;
                    g_adst[row * 4 + (tx >> 2)] = pd;
                }
            } else {
                ps += __shfl_xor_sync(0xffffffffu, ps, 4);
                pd += __shfl_xor_sync(0xffffffffu, pd, 4);
                ps += __shfl_xor_sync(0xffffffffu, ps, 8);
                pd += __shfl_xor_sync(0xffffffffu, pd, 8);
                if (tx == 0 && row < NN) {
                    g_asrc[row] = ps;
                    g_adst[row] = pd;
                }
            }
        }
    }
}

// ---------------- per-edge weight precompute (lane-parallel, natural order) -
__device__ void wgt4_phase() {
    const int gt = blockIdx.x * NTHR + threadIdx.x;
    if (gt < 128) g_stat[gt] = 0.f;   // re-zero BN stat for upcoming post4
    for (int e = gt; e < EE; e += GRID * NTHR) {
        int2 ed = g_edge[e];
        float4 av = *reinterpret_cast<const float4*>(&g_asrc[ed.x * 4]);
        float4 dv = *reinterpret_cast<const float4*>(&g_adst[ed.y * 4]);
        float4 w;
        w.x = __expf(lrelu(av.x + dv.x));
        w.y = __expf(lrelu(av.y + dv.y));
        w.z = __expf(lrelu(av.z + dv.z));
        w.w = __expf(lrelu(av.w + dv.w));
        *reinterpret_cast<float4*>(&g_w[(size_t)e * 4]) = w;
    }
}

// ---------------- edge aggregation: channel-pair layout ---------------------
// Lane owns channels (2*lane, 2*lane+1), both in head lane>>3.
// Per 8-edge chunk: 8 int2 + 8 w-broadcast + 8 float2 hv + 24 FMA.
__device__ void eagg4_phase(const float* __restrict__ h) {
    const int lane = threadIdx.x & 31;
    const int w = (blockIdx.x * NTHR + threadIdx.x) >> 5;
    const int e0 = w * EPW;
    if (e0 >= EE) return;
    const int e1 = min(e0 + EPW, EE);
    const int cc = 2 * lane;          // channel pair base
    const int head = lane >> 3;       // 0..3
    const bool sslane = (lane & 7) == 0;

    float accx = 0.f, accy = 0.f, ss = 0.f;
    int dcur = g_edge[e0].y;

    for (int base = e0; base < e1; base += 8) {   // e0,e1 multiples of 8
        int2 ed[8];
#pragma unroll
        for (int j = 0; j < 8; j++) ed[j] = g_edge[base + j];   // broadcast
        float wv[8];
#pragma unroll
        for (int j = 0; j < 8; j++)
            wv[j] = g_w[(size_t)(base + j) * 4 + head];          // 4-way broadcast
        float2 hv[8];
#pragma unroll
        for (int j = 0; j < 8; j++)
            hv[j] = *reinterpret_cast<const float2*>(&h[(size_t)ed[j].x * 64 + cc]);
#pragma unroll
        for (int j = 0; j < 8; j++) {
            if (ed[j].y != dcur) {       // uniform branch
                atomicAdd(&g_acc[(size_t)dcur * 64 + cc], accx);
                atomicAdd(&g_acc[(size_t)dcur * 64 + cc + 1], accy);
                if (sslane) atomicAdd(&g_sum[dcur * 4 + head], ss);
                accx = accy = ss = 0.f;
                dcur = ed[j].y;
            }
            accx += wv[j] * hv[j].x;
            accy += wv[j] * hv[j].y;
            ss += wv[j];
        }
    }
    atomicAdd(&g_acc[(size_t)dcur * 64 + cc], accx);
    atomicAdd(&g_acc[(size_t)dcur * 64 + cc + 1], accy);
    if (sslane) atomicAdd(&g_sum[dcur * 4 + head], ss);
}

// H=1 C=40: inline exp (1 MUFU/edge), channel pairs on lanes 0..19.
__device__ void eagg1_phase(const float* __restrict__ h) {
    const int lane = threadIdx.x & 31;
    const int w = (blockIdx.x * NTHR + threadIdx.x) >> 5;
    const int e0 = w * EPW;
    if (e0 >= EE) return;
    const int e1 = min(e0 + EPW, EE);
    const int cc = 2 * lane;
    const bool act = lane < 20;       // 40 channels

    float accx = 0.f, accy = 0.f, ss = 0.f;
    int dcur = g_edge[e0].y;

    for (int base = e0; base < e1; base += 8) {
        int2 ed[8];
#pragma unroll
        for (int j = 0; j < 8; j++) ed[j] = g_edge[base + j];
        float wv[8];
#pragma unroll
        for (int j = 0; j < 8; j++)
            wv[j] = __expf(lrelu(g_asrc[ed[j].x] + g_adst[ed[j].y]));  // broadcast loads
        float2 hv[8];
#pragma unroll
        for (int j = 0; j < 8; j++)
            hv[j] = act ? *reinterpret_cast<const float2*>(&h[(size_t)ed[j].x * 40 + cc])
                        : make_float2(0.f, 0.f);
#pragma unroll
        for (int j = 0; j < 8; j++) {
            if (ed[j].y != dcur) {
                if (act) {
                    atomicAdd(&g_acc[(size_t)dcur * 64 + cc], accx);
                    atomicAdd(&g_acc[(size_t)dcur * 64 + cc + 1], accy);
                }
                if (lane == 0) atomicAdd(&g_sum[dcur * 4], ss);
                accx = accy = ss = 0.f;
                dcur = ed[j].y;
            }
            accx += wv[j] * hv[j].x;
            accy += wv[j] * hv[j].y;
            ss += wv[j];
        }
    }
    if (act) {
        atomicAdd(&g_acc[(size_t)dcur * 64 + cc], accx);
        atomicAdd(&g_acc[(size_t)dcur * 64 + cc + 1], accy);
    }
    if (lane == 0) atomicAdd(&g_sum[dcur * 4], ss);
}

// ---------------- post phases ------------------------------------------------
__device__ void post4_phase(float* sm, const float* __restrict__ h,
                            const float* __restrict__ bias, float* __restrict__ out) {
    const int c = threadIdx.x & 63;    // constant per thread (stride % 64 == 0)
    const int head = c >> 4;
    const float bs = bias[c];
    float s_acc = 0.f, q_acc = 0.f;
    for (int idx = blockIdx.x * NTHR + threadIdx.x; idx < NN * 64; idx += GRID * NTHR) {
        int v = idx >> 6;
        float ws = __expf(lrelu(g_asrc[v * 4 + head] + g_adst[v * 4 + head]));
        float o = (g_acc[idx] + ws * h[idx]) / (g_sum[v * 4 + head] + ws + 1e-16f) + bs;
        out[idx] = o;
        g_acc[idx] = 0.f;
        s_acc += o;
        q_acc += o * o;
    }
    float* shs = sm;
    float* shq = sm + 256;
    shs[threadIdx.x] = s_acc;
    shq[threadIdx.x] = q_acc;
    __syncthreads();
    if (threadIdx.x < 64) {
        float s = shs[threadIdx.x] + shs[threadIdx.x + 64] + shs[threadIdx.x + 128] + shs[threadIdx.x + 192];
        float q = shq[threadIdx.x] + shq[threadIdx.x + 64] + shq[threadIdx.x + 128] + shq[threadIdx.x + 192];
        atomicAdd(&g_stat[threadIdx.x], s);
        atomicAdd(&g_stat[64 + threadIdx.x], q);
    }
    __syncthreads();
}

__device__ void post1_phase(const float* __restrict__ h, const float* __restrict__ bias,
                            float* __restrict__ out) {
    const int lane = threadIdx.x & 31;
    const int warp0 = (blockIdx.x * NTHR + threadIdx.x) >> 5;
    const int c0 = lane, c1 = lane + 32;
    const bool use1 = lane < 8;
    for (int gw = warp0; gw < NN; gw += NWARP) {
        float ws = __expf(lrelu(g_asrc[gw] + g_adst[gw]));
        float inv = 1.f / (g_sum[gw * 4] + ws + 1e-16f);
        float a0 = g_acc[(size_t)gw * 64 + c0];
        float a1 = use1 ? g_acc[(size_t)gw * 64 + c1] : 0.f;
        float o0 = (a0 + ws * h[(size_t)gw * 40 + c0]) * inv + bias[c0];
        float o1 = use1 ? ((a1 + ws * h[(size_t)gw * 40 + c1]) * inv + bias[c1]) : neg_inf();
        float m = fmaxf(o0, o1);
#pragma unroll
        for (int off = 16; off; off >>= 1) m = fmaxf(m, __shfl_xor_sync(0xffffffffu, m, off));
        float se = __expf(o0 - m) + (use1 ? __expf(o1 - m) : 0.f);
#pragma unroll
        for (int off = 16; off; off >>= 1) se += __shfl_xor_sync(0xffffffffu, se, off);
        float ls = __logf(se);
        out[(size_t)gw * 40 + c0] = o0 - m - ls;
        if (use1) out[(size_t)gw * 40 + c1] = o1 - m - ls;
    }
}

// ---------------- THE mega-kernel --------------------------------------------
__global__ __launch_bounds__(NTHR, 4) void k_mega(
    const float* __restrict__ x, const int* __restrict__ ei,
    const float* __restrict__ W0, const float* __restrict__ as0, const float* __restrict__ ad0,
    const float* __restrict__ b0, const float* __restrict__ g0, const float* __restrict__ be0,
    const float* __restrict__ W1, const float* __restrict__ as1, const float* __restrict__ ad1,
    const float* __restrict__ b1, const float* __restrict__ g1, const float* __restrict__ be1,
    const float* __restrict__ W2, const float* __restrict__ as2, const float* __restrict__ ad2,
    const float* __restrict__ b2, float* __restrict__ out) {
    __shared__ float smbuf[4480];
    __shared__ float bnsc[64], bnsh[64];
    __shared__ int s_tile;
    const int tid = threadIdx.x;
    const int gt = blockIdx.x * NTHR + tid;

    // P0: zero scratch (g_sum zeroed per-layer inside gemm_phase)
    {
        float4 z = make_float4(0.f, 0.f, 0.f, 0.f);
        float4* a4 = reinterpret_cast<float4*>(g_acc);
        for (int i = gt; i < NN * 16; i += GRID * NTHR) a4[i] = z;
        for (int i = gt; i < NN; i += GRID * NTHR) g_cursor[i] = 0;
        if (gt < 128) g_stat[gt] = 0.f;
        if (gt < 3) g_tilec[gt] = 0;
    }
    gridsync();

    // P1: count in-degrees
    for (int e = gt; e < EE; e += GRID * NTHR)
        atomicAdd(&g_cursor[ei[EE + e]], 1);
    gridsync();

    // P2: per-block local exclusive scan of counts
    const int CH = (NN + GRID - 1) / GRID;   // 83
    const int start = blockIdx.x * CH;
    int* si = (int*)smbuf;
    for (int i = tid; i < CH; i += NTHR)
        si[i] = (start + i < NN) ? g_cursor[start + i] : 0;
    __syncthreads();
    if (tid == 0) {
        int run = 0;
        for (int i = 0; i < CH; i++) { int v = si[i]; si[i] = run; run += v; }
        si[CH] = run;
        g_part[blockIdx.x] = run;
    }
    __syncthreads();
    gridsync();

    // P3: block 0 scans block totals
    if (blockIdx.x == 0) {
        int* sp = (int*)(smbuf + 2304);
        for (int i = tid; i < GRID; i += NTHR) sp[i] = g_part[i];
        __syncthreads();
        if (tid == 0) {
            int run = 0;
            for (int i = 0; i < GRID; i++) { int v = sp[i]; sp[i] = run; run += v; }
        }
        __syncthreads();
        for (int i = tid; i < GRID; i += NTHR) g_partpre[i] = sp[i];
    }
    gridsync();

    // P4: write rowptr + scatter cursors
    {
        const int base = g_partpre[blockIdx.x];
        for (int i = tid; i < CH; i += NTHR) {
            int v = start + i;
            if (v < NN) {
                int rp = base + si[i];
                g_rowptr[v] = rp;
                g_cursor[v] = rp;
            }
        }
        if (blockIdx.x == 0 && tid == 0) g_rowptr[NN] = EE;
    }
    gridsync();

    // P5: scatter edges into CSR (dst-sorted, packed int2)
    for (int e = gt; e < EE; e += GRID * NTHR) {
        int s = ei[e];
        int d = ei[EE + e];
        int pos = atomicAdd(&g_cursor[d], 1);
        g_edge[pos] = make_int2(s, d);
    }
    gridsync();

    // ---- layer 0 ----
    gemm_phase<128, 64, false, 4>(smbuf, bnsc, bnsh, &s_tile, &g_tilec[0],
                                  x, W0, g_h, as0, ad0, g0, be0);
    gridsync();
    wgt4_phase();
    gridsync();
    eagg4_phase(g_h);
    gridsync();
    post4_phase(smbuf, g_h, b0, g_agg);
    gridsync();

    // ---- layer 1 ----
    gemm_phase<64, 64, true, 4>(smbuf, bnsc, bnsh, &s_tile, &g_tilec[1],
                                g_agg, W1, g_h, as1, ad1, g0, be0);
    gridsync();
    wgt4_phase();
    gridsync();
    eagg4_phase(g_h);
    gridsync();
    post4_phase(smbuf, g_h, b1, g_agg);
    gridsync();

    // ---- layer 2 ----
    gemm_phase<64, 40, true, 1>(smbuf, bnsc, bnsh, &s_tile, &g_tilec[2],
                                g_agg, W2, g_h, as2, ad2, g1, be1);
    gridsync();
    eagg1_phase(g_h);
    gridsync();
    post1_phase(g_h, b2, out);
}

// ---------------- launch ------------------------------------------------------
extern "C" void kernel_launch(void* const* d_in, const int* in_sizes, int n_in,
                              void* d_out, int out_size) {
    const float* x   = (const float*)d_in[0];
    const int*   ei  = (const int*)d_in[1];
    const float* W0  = (const float*)d_in[2];
    const float* as0 = (const float*)d_in[3];
    const float* ad0 = (const float*)d_in[4];
    const float* b0  = (const float*)d_in[5];
    const float* g0  = (const float*)d_in[6];
    const float* be0 = (const float*)d_in[7];
    const float* W1  = (const float*)d_in[8];
    const float* as1 = (const float*)d_in[9];
    const float* ad1 = (const float*)d_in[10];
    const float* b1  = (const float*)d_in[11];
    const float* g1  = (const float*)d_in[12];
    const float* be1 = (const float*)d_in[13];
    const float* W2  = (const float*)d_in[14];
    const float* as2 = (const float*)d_in[15];
    const float* ad2 = (const float*)d_in[16];
    const float* b2  = (const float*)d_in[17];
    float* out = (float*)d_out;

    k_mega<<<GRID, NTHR>>>(x, ei, W0, as0, ad0, b0, g0, be0,
                           W1, as1, ad1, b1, g1, be1,
                           W2, as2, ad2, b2, out);
}